// round 9
// baseline (speedup 1.0000x reference)
#include <cuda_runtime.h>
#include <cuda_bf16.h>
#include <mma.h>
#include <cstdint>

using namespace nvcuda;

#define N_B    4
#define S_LEN  2048
#define EMB    1024
#define HEADS  16
#define HD     64
#define MWORDS (S_LEN / 32)

#define PT   72    // bf16 smem pitch (144 B rows)
#define PSCR 20

// ---------------- scratch (device globals) ---------------------------------
__device__ __nv_bfloat16 g_qh[N_B * HEADS * S_LEN * HD];
__device__ __nv_bfloat16 g_ql[N_B * HEADS * S_LEN * HD];
__device__ __nv_bfloat16 g_kh[N_B * HEADS * S_LEN * HD];
__device__ __nv_bfloat16 g_kl[N_B * HEADS * S_LEN * HD];
__device__ __nv_bfloat16 g_vh[N_B * HEADS * S_LEN * HD];
__device__ __nv_bfloat16 g_vl[N_B * HEADS * S_LEN * HD];
__device__ __nv_bfloat16 g_aoh[N_B * S_LEN * EMB];
__device__ __nv_bfloat16 g_aol[N_B * S_LEN * EMB];
__device__ __nv_bfloat16 g_woh[EMB * EMB];
__device__ __nv_bfloat16 g_wol[EMB * EMB];
__device__ unsigned g_mbits[N_B * S_LEN * MWORDS];

__device__ __forceinline__ void split2(float x0, float x1, uint32_t& hi, uint32_t& lo) {
    __nv_bfloat16 h0 = __float2bfloat16_rn(x0), h1 = __float2bfloat16_rn(x1);
    float r0 = x0 - __bfloat162float(h0), r1 = x1 - __bfloat162float(h1);
    __nv_bfloat16 l0 = __float2bfloat16_rn(r0), l1 = __float2bfloat16_rn(r1);
    __nv_bfloat162 hp; hp.x = h0; hp.y = h1;
    __nv_bfloat162 lp; lp.x = l0; lp.y = l1;
    hi = *reinterpret_cast<uint32_t*>(&hp);
    lo = *reinterpret_cast<uint32_t*>(&lp);
}

__device__ __forceinline__ uint32_t smem_u32(const void* p) {
    uint32_t a;
    asm("{ .reg .u64 t; cvta.to.shared.u64 t, %1; cvt.u32.u64 %0, t; }"
        : "=r"(a) : "l"(p));
    return a;
}

// ---- tensor-core / async-copy primitives ----------------------------------
__device__ __forceinline__ void ldsm_x4(uint32_t* r, uint32_t addr) {
    asm volatile("ldmatrix.sync.aligned.m8n8.x4.shared.b16 {%0,%1,%2,%3}, [%4];"
                 : "=r"(r[0]), "=r"(r[1]), "=r"(r[2]), "=r"(r[3]) : "r"(addr));
}
__device__ __forceinline__ void ldsm_x4_t(uint32_t* r, uint32_t addr) {
    asm volatile("ldmatrix.sync.aligned.m8n8.x4.trans.shared.b16 {%0,%1,%2,%3}, [%4];"
                 : "=r"(r[0]), "=r"(r[1]), "=r"(r[2]), "=r"(r[3]) : "r"(addr));
}
__device__ __forceinline__ void mma16816(float* d, const uint32_t* a, const uint32_t* b) {
    asm volatile(
        "mma.sync.aligned.m16n8k16.row.col.f32.bf16.bf16.f32 "
        "{%0,%1,%2,%3}, {%4,%5,%6,%7}, {%8,%9}, {%0,%1,%2,%3};"
        : "+f"(d[0]), "+f"(d[1]), "+f"(d[2]), "+f"(d[3])
        : "r"(a[0]), "r"(a[1]), "r"(a[2]), "r"(a[3]), "r"(b[0]), "r"(b[1]));
}
__device__ __forceinline__ void cp16(uint32_t dst, const void* src) {
    asm volatile("cp.async.cg.shared.global [%0], [%1], 16;" :: "r"(dst), "l"(src));
}
#define CP_COMMIT() asm volatile("cp.async.commit_group;" ::: "memory")
#define CP_WAIT0()  asm volatile("cp.async.wait_group 0;" ::: "memory")
#define CP_WAIT1()  asm volatile("cp.async.wait_group 1;" ::: "memory")

// stage nrows x 64 f32 -> bf16 hi/lo smem pitch PT (proj only)
__device__ __forceinline__ void stage_rows_f32(const float* __restrict__ src, size_t stride,
                                               char* s_hi, char* s_lo, int t)
{
    const int r    = t >> 1;
    const int half = t & 1;
    const float4* s4 = (const float4*)(src + (size_t)r * stride) + half * 8;
#pragma unroll
    for (int tt = 0; tt < 4; tt++) {
        float4 a = s4[2 * tt], b = s4[2 * tt + 1];
        float f[8] = {a.x, a.y, a.z, a.w, b.x, b.y, b.z, b.w};
        uint32_t H[4], L[4];
#pragma unroll
        for (int u = 0; u < 4; u++) split2(f[2 * u], f[2 * u + 1], H[u], L[u]);
        uint32_t off = (uint32_t)(r * (PT * 2) + half * 64 + tt * 16);
        *(uint4*)(s_hi + off) = make_uint4(H[0], H[1], H[2], H[3]);
        *(uint4*)(s_lo + off) = make_uint4(L[0], L[1], L[2], L[3]);
    }
}

// ---------------------------------------------------------------------------
// Kernel 0a: pack mask bits
// ---------------------------------------------------------------------------
__global__ __launch_bounds__(256)
void mask_pack_kernel(const int* __restrict__ mask)
{
    int gid  = blockIdx.x * 256 + threadIdx.x;
    int w    = gid >> 5;
    int lane = gid & 31;
    int v = mask[(size_t)w * 32 + lane];
    unsigned bits = __ballot_sync(0xffffffffu, v != 0);
    if (lane == 0) g_mbits[w] = bits;
}

// ---------------------------------------------------------------------------
// Kernel 0b: pre-split Wo (once)
// ---------------------------------------------------------------------------
__global__ __launch_bounds__(256)
void wo_split_kernel(const float* __restrict__ Wo)
{
    size_t idx = ((size_t)blockIdx.x * 256 + threadIdx.x) * 8;
    float4 a = *(const float4*)(Wo + idx);
    float4 b = *(const float4*)(Wo + idx + 4);
    float f[8] = {a.x, a.y, a.z, a.w, b.x, b.y, b.z, b.w};
    uint32_t H[4], L[4];
#pragma unroll
    for (int u = 0; u < 4; u++) split2(f[2 * u], f[2 * u + 1], H[u], L[u]);
    *(uint4*)(g_woh + idx) = make_uint4(H[0], H[1], H[2], H[3]);
    *(uint4*)(g_wol + idx) = make_uint4(L[0], L[1], L[2], L[3]);
}

// ---------------------------------------------------------------------------
// Kernel 1: projections (unchanged)
// ---------------------------------------------------------------------------
#define PJ_WHI 0
#define PJ_WLO 9216
#define PJ_XHI 18432
#define PJ_XLO 36864
#define PJ_SCR 55296
#define PJ_SMEM (55296 + 10240)

__global__ __launch_bounds__(256, 2)
void proj_wmma_kernel(const float* __restrict__ xq, const float* __restrict__ xk,
                      const float* __restrict__ xv,
                      const float* __restrict__ Wq, const float* __restrict__ Wk,
                      const float* __restrict__ Wv)
{
    extern __shared__ char sm[];
    __nv_bfloat16* Whi = (__nv_bfloat16*)(sm + PJ_WHI);
    __nv_bfloat16* Wlo = (__nv_bfloat16*)(sm + PJ_WLO);
    __nv_bfloat16* Xhi = (__nv_bfloat16*)(sm + PJ_XHI);
    __nv_bfloat16* Xlo = (__nv_bfloat16*)(sm + PJ_XLO);

    const int which = blockIdx.z;
    const float* X; const float* W; __nv_bfloat16* Yh; __nv_bfloat16* Yl;
    if (which == 0)      { X = xq; W = Wq; Yh = g_qh; Yl = g_ql; }
    else if (which == 1) { X = xk; W = Wk; Yh = g_kh; Yl = g_kl; }
    else                 { X = xv; W = Wv; Yh = g_vh; Yl = g_vl; }

    const int nh = blockIdx.y;
    const int n  = nh / HEADS;
    const int h  = nh % HEADS;
    const int s0 = blockIdx.x * 128;
    const int tid = threadIdx.x, wid = tid >> 5, lane = tid & 31;
    float* scr = (float*)(sm + PJ_SCR) + wid * (16 * PSCR);

    stage_rows_f32(X + (size_t)(n * S_LEN + s0) * EMB + h * HD, EMB,
                   (char*)Xhi, (char*)Xlo, tid);
    if (tid < 128)
        stage_rows_f32(W, HD, (char*)Whi, (char*)Wlo, tid);
    __syncthreads();

    wmma::fragment<wmma::accumulator, 16, 16, 16, float> acc[4];
#pragma unroll
    for (int j = 0; j < 4; j++) wmma::fill_fragment(acc[j], 0.0f);

#pragma unroll
    for (int kk = 0; kk < 4; kk++) {
        wmma::fragment<wmma::matrix_a, 16, 16, 16, __nv_bfloat16, wmma::row_major> ah, al;
        wmma::load_matrix_sync(ah, Xhi + wid * 16 * PT + kk * 16, PT);
        wmma::load_matrix_sync(al, Xlo + wid * 16 * PT + kk * 16, PT);
#pragma unroll
        for (int j = 0; j < 4; j++) {
            wmma::fragment<wmma::matrix_b, 16, 16, 16, __nv_bfloat16, wmma::col_major> bh, bl;
            wmma::load_matrix_sync(bh, Whi + j * 16 * PT + kk * 16, PT);
            wmma::load_matrix_sync(bl, Wlo + j * 16 * PT + kk * 16, PT);
            wmma::mma_sync(acc[j], ah, bh, acc[j]);
            wmma::mma_sync(acc[j], ah, bl, acc[j]);
            wmma::mma_sync(acc[j], al, bh, acc[j]);
        }
    }

    const int r = lane >> 1, cw = lane & 1;
    const size_t ybase = (size_t)((n * HEADS + h) * S_LEN + s0 + wid * 16) * HD;
#pragma unroll
    for (int j = 0; j < 4; j++) {
        wmma::store_matrix_sync(scr, acc[j], PSCR, wmma::mem_row_major);
        __syncwarp();
        const float* s = scr + r * PSCR + cw * 8;
        uint32_t H[4], L[4];
#pragma unroll
        for (int u = 0; u < 4; u++) split2(s[2 * u], s[2 * u + 1], H[u], L[u]);
        const size_t off = ybase + (size_t)r * HD + j * 16 + cw * 8;
        *(uint4*)(Yh + off) = make_uint4(H[0], H[1], H[2], H[3]);
        *(uint4*)(Yl + off) = make_uint4(L[0], L[1], L[2], L[3]);
        __syncwarp();
    }
}

// ---------------------------------------------------------------------------
// Kernel 2: flash attention — 4-wide MMA interleave, 3-stage cp.async ring
// grid (HEADS, S_LEN/128, N_B), 256 threads, kv-tile 32
// ---------------------------------------------------------------------------
#define A_QHI  0
#define A_QLO  18432
#define A_RING 36864
#define KV_SZ  18432
#define KV_KLO 4608
#define KV_VHI 9216
#define KV_VLO 13824
#define ATTN_SMEM (36864 + 3 * 18432 + 256)
#define NIT (S_LEN / 32)

__global__ __launch_bounds__(256, 2)
void attn_mma_kernel()
{
    extern __shared__ char sm[];
    const int tid = threadIdx.x, wid = tid >> 5, lane = tid & 31;
    const int h = blockIdx.x, qt = blockIdx.y, n = blockIdx.z;
    const int q0 = qt * 128;

    const size_t head_base = (size_t)(n * HEADS + h) * S_LEN * HD;
    const __nv_bfloat16* Qh = g_qh + head_base + (size_t)q0 * HD;
    const __nv_bfloat16* Ql = g_ql + head_base + (size_t)q0 * HD;
    const __nv_bfloat16* Kh = g_kh + head_base;
    const __nv_bfloat16* Kl = g_kl + head_base;
    const __nv_bfloat16* Vh = g_vh + head_base;
    const __nv_bfloat16* Vl = g_vl + head_base;

    const uint32_t smb = smem_u32(sm);

    // ---- prologue: prefetch KV tiles 0 and 1 ----
    const int str = tid >> 3, soct = tid & 7;
    const uint32_t soff = (uint32_t)(str * (PT * 2) + soct * 16);
#pragma unroll
    for (int pt = 0; pt < 2; pt++) {
        const size_t gsrc = (size_t)(pt * 32 + str) * HD + soct * 8;
        const uint32_t d = smb + A_RING + pt * KV_SZ + soff;
        cp16(d,           Kh + gsrc);
        cp16(d + KV_KLO,  Kl + gsrc);
        cp16(d + KV_VHI,  Vh + gsrc);
        cp16(d + KV_VLO,  Vl + gsrc);
        CP_COMMIT();
    }

    // ---- stage Q, hoist fragments ----
    {
        const int r = tid >> 1, half = tid & 1;
        const char* sh0 = (const char*)(Qh + (size_t)r * HD + half * 32);
        const char* sl0 = (const char*)(Ql + (size_t)r * HD + half * 32);
        uint32_t off = (uint32_t)(r * (PT * 2) + half * 64);
#pragma unroll
        for (int tt = 0; tt < 4; tt++) {
            *(uint4*)(sm + A_QHI + off + tt * 16) = *(const uint4*)(sh0 + tt * 16);
            *(uint4*)(sm + A_QLO + off + tt * 16) = *(const uint4*)(sl0 + tt * 16);
        }
    }
    __syncthreads();

    const int l7  = lane & 7;
    const int s01 = (lane >> 3) & 1;
    const int s23 = (lane >> 4) & 1;

    uint32_t qh[4][4], ql[4][4];
    {
        uint32_t base = smb + (uint32_t)((wid * 16 + l7 + s01 * 8) * (PT * 2)) + s23 * 16;
#pragma unroll
        for (int c = 0; c < 4; c++) {
            ldsm_x4(qh[c], base + A_QHI + c * 32);
            ldsm_x4(ql[c], base + A_QLO + c * 32);
        }
    }

    const int g   = lane >> 2;
    const int tig = lane & 3;
    const int qrow_g  = q0 + wid * 16 + g;
    const unsigned* mrow0 = g_mbits + (size_t)(n * S_LEN + qrow_g) * MWORDS;
    const unsigned* mrow8 = mrow0 + 8 * MWORDS;

    const uint32_t kqoff = (uint32_t)(((lane >> 4) * 8 + l7) * (PT * 2)) + ((lane >> 3) & 1) * 16;
    const uint32_t voff  = (uint32_t)((((lane >> 3) & 1) * 8 + l7) * (PT * 2)) + (lane >> 4) * 16;

    float o[8][4];
#pragma unroll
    for (int j = 0; j < 8; j++)
#pragma unroll
        for (int u = 0; u < 4; u++) o[j][u] = 0.f;
    float lsum_g = 0.f, lsum_8 = 0.f;

    const float SC = 0.03125f;

    for (int it = 0; it < NIT; it++) {
        const uint32_t kv = smb + A_RING + (it % 3) * KV_SZ;

        CP_WAIT1();            // tile `it` resident (one prefetch still in flight)
        __syncthreads();

        // prefetch tile it+2 into ring slot (it+2)%3 (reader of that slot was iter it-1)
        if (it + 2 < NIT) {
            const size_t gsrc = (size_t)((it + 2) * 32 + str) * HD + soct * 8;
            const uint32_t d = smb + A_RING + ((it + 2) % 3) * KV_SZ + soff;
            cp16(d,           Kh + gsrc);
            cp16(d + KV_KLO,  Kl + gsrc);
            cp16(d + KV_VHI,  Vh + gsrc);
            cp16(d + KV_VLO,  Vl + gsrc);
        }
        CP_COMMIT();           // commit every iter to keep group counts aligned

        // ---- S = Q K^T : 4 independent accumulator chains interleaved ----
        float s[4][4];
#pragma unroll
        for (int j = 0; j < 4; j++)
#pragma unroll
            for (int u = 0; u < 4; u++) s[j][u] = 0.f;

#pragma unroll
        for (int c = 0; c < 4; c++) {
            uint32_t bh0[4], bl0[4], bh1[4], bl1[4];
            const uint32_t ka0 = kv + kqoff + c * 32;
            const uint32_t ka1 = ka0 + (uint32_t)(16 * (PT * 2));
            ldsm_x4(bh0, ka0); ldsm_x4(bl0, ka0 + KV_KLO);
            ldsm_x4(bh1, ka1); ldsm_x4(bl1, ka1 + KV_KLO);
            mma16816(s[0], qh[c], bh0); mma16816(s[1], qh[c], bh0 + 2);
            mma16816(s[2], qh[c], bh1); mma16816(s[3], qh[c], bh1 + 2);
            mma16816(s[0], qh[c], bl0); mma16816(s[1], qh[c], bl0 + 2);
            mma16816(s[2], qh[c], bl1); mma16816(s[3], qh[c], bl1 + 2);
            mma16816(s[0], ql[c], bh0); mma16816(s[1], ql[c], bh0 + 2);
            mma16816(s[2], ql[c], bh1); mma16816(s[3], ql[c], bh1 + 2);
        }

        // ---- softmax in registers ----
        const unsigned w0 = mrow0[it];
        const unsigned w8 = mrow8[it];
#pragma unroll
        for (int j = 0; j < 4; j++) {
            const int bit = j * 8 + tig * 2;
            float p0 = __expf(s[j][0] * SC);
            float p1 = __expf(s[j][1] * SC);
            float p2 = __expf(s[j][2] * SC);
            float p3 = __expf(s[j][3] * SC);
            p0 = ((w0 >> bit) & 1u)       ? p0 : 0.f;
            p1 = ((w0 >> (bit + 1)) & 1u) ? p1 : 0.f;
            p2 = ((w8 >> bit) & 1u)       ? p2 : 0.f;
            p3 = ((w8 >> (bit + 1)) & 1u) ? p3 : 0.f;
            lsum_g += p0 + p1;
            lsum_8 += p2 + p3;
            s[j][0] = p0; s[j][1] = p1; s[j][2] = p2; s[j][3] = p3;
        }

        // ---- O += P V : 4 accumulator chains per jp-pair interleaved ----
#pragma unroll
        for (int c2 = 0; c2 < 2; c2++) {
            uint32_t ah[4], al[4];
            split2(s[2 * c2][0],     s[2 * c2][1],     ah[0], al[0]);
            split2(s[2 * c2][2],     s[2 * c2][3],     ah[1], al[1]);
            split2(s[2 * c2 + 1][0], s[2 * c2 + 1][1], ah[2], al[2]);
            split2(s[2 * c2 + 1][2], s[2 * c2 + 1][3], ah[3], al[3]);
#pragma unroll
            for (int jpp = 0; jpp < 2; jpp++) {
                uint32_t bh0[4], bl0[4], bh1[4], bl1[4];
                const uint32_t va0 = kv + KV_VHI + voff +
                                     (uint32_t)(c2 * 16 * (PT * 2)) + jpp * 64;
                const uint32_t va1 = va0 + 32;
                ldsm_x4_t(bh0, va0); ldsm_x4_t(bl0, va0 + (KV_VLO - KV_VHI));
                ldsm_x4_t(bh1, va1); ldsm_x4_t(bl1, va1 + (KV_VLO - KV_VHI));
                float* o0 = o[4 * jpp + 0];
                float* o1 = o[4 * jpp + 1];
                float* o2 = o[4 * jpp + 2];
                float* o3 = o[4 * jpp + 3];
                mma16816(o0, ah, bh0); mma16816(o1, ah, bh0 + 2);
                mma16816(o2, ah, bh1); mma16816(o3, ah, bh1 + 2);
                mma16816(o0, ah, bl0); mma16816(o1, ah, bl0 + 2);
                mma16816(o2, ah, bl1); mma16816(o3, ah, bl1 + 2);
                mma16816(o0, al, bh0); mma16816(o1, al, bh0 + 2);
                mma16816(o2, al, bh1); mma16816(o3, al, bh1 + 2);
            }
        }
    }

    // ---- epilogue ----
    lsum_g += __shfl_xor_sync(0xffffffffu, lsum_g, 1);
    lsum_g += __shfl_xor_sync(0xffffffffu, lsum_g, 2);
    lsum_8 += __shfl_xor_sync(0xffffffffu, lsum_8, 1);
    lsum_8 += __shfl_xor_sync(0xffffffffu, lsum_8, 2);
    const float inv_g = 1.0f / lsum_g;
    const float inv_8 = 1.0f / lsum_8;

    const size_t d0 = (size_t)(n * S_LEN + qrow_g) * EMB + h * HD;
    const size_t d8 = d0 + (size_t)8 * EMB;
#pragma unroll
    for (int j = 0; j < 8; j++) {
        const int col = j * 8 + tig * 2;
        uint32_t H, L;
        split2(o[j][0] * inv_g, o[j][1] * inv_g, H, L);
        *(uint32_t*)(g_aoh + d0 + col) = H;
        *(uint32_t*)(g_aol + d0 + col) = L;
        split2(o[j][2] * inv_8, o[j][3] * inv_8, H, L);
        *(uint32_t*)(g_aoh + d8 + col) = H;
        *(uint32_t*)(g_aol + d8 + col) = L;
    }
}

// ---------------------------------------------------------------------------
// Kernel 3: output projection — 3-stage cp.async ring, BK=16
// ---------------------------------------------------------------------------
#define PK 24
#define OB_SZ   24576
#define OB_ALO  6144
#define OB_BHI  12288
#define OB_BLO  18432
#define O_SCR   (3 * 24576)
#define OUT_SMEM (3 * 24576 + 10240)
#define ONIT (EMB / 16)

__global__ __launch_bounds__(256, 2)
void out_wmma_kernel(const float* __restrict__ bo, float* __restrict__ out)
{
    extern __shared__ char sm[];
    const uint32_t smb = smem_u32(sm);

    const int tid = threadIdx.x, wid = tid >> 5, lane = tid & 31;
    const int r0 = blockIdx.y * 128;
    const int e0 = blockIdx.x * 128;
    const int wr = wid & 3;
    const int wc = wid >> 2;
    float* scr = (float*)(sm + O_SCR) + wid * (16 * PSCR);

    wmma::fragment<wmma::accumulator, 16, 16, 16, float> acc[2][4];
#pragma unroll
    for (int i = 0; i < 2; i++)
#pragma unroll
        for (int j = 0; j < 4; j++) wmma::fill_fragment(acc[i][j], 0.0f);

    const int sr = tid >> 1;
    const int sh = tid & 1;
    const uint32_t soff = (uint32_t)(sr * (PK * 2) + sh * 16);
    const size_t abase = (size_t)(r0 + sr) * EMB + sh * 8;
    const size_t bbase = (size_t)(e0 + sr) * EMB + sh * 8;

#pragma unroll
    for (int pt = 0; pt < 2; pt++) {
        const uint32_t d = smb + pt * OB_SZ + soff;
        cp16(d,          g_aoh + abase + pt * 16);
        cp16(d + OB_ALO, g_aol + abase + pt * 16);
        cp16(d + OB_BHI, g_woh + bbase + pt * 16);
        cp16(d + OB_BLO, g_wol + bbase + pt * 16);
        CP_COMMIT();
    }

    for (int ic = 0; ic < ONIT; ic++) {
        const char* buf = sm + (ic % 3) * OB_SZ;

        CP_WAIT1();
        __syncthreads();

        if (ic + 2 < ONIT) {
            const uint32_t d = smb + ((ic + 2) % 3) * OB_SZ + soff;
            cp16(d,          g_aoh + abase + (ic + 2) * 16);
            cp16(d + OB_ALO, g_aol + abase + (ic + 2) * 16);
            cp16(d + OB_BHI, g_woh + bbase + (ic + 2) * 16);
            cp16(d + OB_BLO, g_wol + bbase + (ic + 2) * 16);
        }
        CP_COMMIT();

        const __nv_bfloat16* Ahi = (const __nv_bfloat16*)(buf);
        const __nv_bfloat16* Alo = (const __nv_bfloat16*)(buf + OB_ALO);
        const __nv_bfloat16* Bhi = (const __nv_bfloat16*)(buf + OB_BHI);
        const __nv_bfloat16* Blo = (const __nv_bfloat16*)(buf + OB_BLO);

        wmma::fragment<wmma::matrix_a, 16, 16, 16, __nv_bfloat16, wmma::row_major> ah[2], al[2];
#pragma unroll
        for (int i = 0; i < 2; i++) {
            wmma::load_matrix_sync(ah[i], Ahi + (wr * 32 + i * 16) * PK, PK);
            wmma::load_matrix_sync(al[i], Alo + (wr * 32 + i * 16) * PK, PK);
        }
#pragma unroll
        for (int j = 0; j < 4; j++) {
            wmma::fragment<wmma::matrix_b, 16, 16, 16, __nv_bfloat16, wmma::col_major> bh, bl;
            wmma::load_matrix_sync(bh, Bhi + (wc * 64 + j * 16) * PK, PK);
            wmma::load_matrix_sync(bl, Blo + (wc * 64 + j * 16) * PK, PK);
            wmma::mma_sync(acc[0][j], ah[0], bh, acc[0][j]);
            wmma::mma_sync(acc[1][j], ah[1], bh, acc[1][j]);
            wmma::mma_sync(acc[0][j], ah[0], bl, acc[0][j]);
            wmma::mma_sync(acc[1][j], ah[1], bl, acc[1][j]);
            wmma::mma_sync(acc[0][j], al[0], bh, acc[0][j]);
            wmma::mma_sync(acc[1][j], al[1], bh, acc[1][j]);
        }
    }

    const int r = lane >> 1, cw = lane & 1;
#pragma unroll
    for (int i = 0; i < 2; i++)
#pragma unroll
        for (int j = 0; j < 4; j++) {
            wmma::store_matrix_sync(scr, acc[i][j], PSCR, wmma::mem_row_major);
            __syncwarp();
            const int row = r0 + wr * 32 + i * 16 + r;
            const int col = e0 + wc * 64 + j * 16 + cw * 8;
            const float4 bv0 = *(const float4*)(bo + col);
            const float4 bv1 = *(const float4*)(bo + col + 4);
            const float* s = scr + r * PSCR + cw * 8;
            float4 o0 = make_float4(s[0] + bv0.x, s[1] + bv0.y, s[2] + bv0.z, s[3] + bv0.w);
            float4 o1 = make_float4(s[4] + bv1.x, s[5] + bv1.y, s[6] + bv1.z, s[7] + bv1.w);
            *(float4*)(out + (size_t)row * EMB + col)     = o0;
            *(float4*)(out + (size_t)row * EMB + col + 4) = o1;
            __syncwarp();
        }
}

// ---------------------------------------------------------------------------
extern "C" void kernel_launch(void* const* d_in, const int* in_sizes, int n_in,
                              void* d_out, int out_size)
{
    const float* values  = (const float*)d_in[0];
    const float* queries = (const float*)d_in[1];
    const float* keys    = (const float*)d_in[2];
    const int*   mask    = (const int*)  d_in[3];
    const float* Wv      = (const float*)d_in[4];
    const float* Wk      = (const float*)d_in[5];
    const float* Wq      = (const float*)d_in[6];
    const float* Wo      = (const float*)d_in[7];
    const float* bo      = (const float*)d_in[8];
    float* out = (float*)d_out;

    static bool attr_set = false;
    if (!attr_set) {
        cudaFuncSetAttribute(proj_wmma_kernel,
                             cudaFuncAttributeMaxDynamicSharedMemorySize, PJ_SMEM);
        cudaFuncSetAttribute(attn_mma_kernel,
                             cudaFuncAttributeMaxDynamicSharedMemorySize, ATTN_SMEM);
        cudaFuncSetAttribute(out_wmma_kernel,
                             cudaFuncAttributeMaxDynamicSharedMemorySize, OUT_SMEM);
        attr_set = true;
    }

    mask_pack_kernel<<<(N_B * S_LEN * MWORDS * 32) / 256, 256>>>(mask);
    wo_split_kernel<<<(EMB * EMB) / (256 * 8), 256>>>(Wo);

    dim3 pgrid(S_LEN / 128, N_B * HEADS, 3);
    proj_wmma_kernel<<<pgrid, 256, PJ_SMEM>>>(queries, keys, values, Wq, Wk, Wv);

    dim3 agrid(HEADS, S_LEN / 128, N_B);
    attn_mma_kernel<<<agrid, 256, ATTN_SMEM>>>();

    dim3 ggrid(EMB / 128, (N_B * S_LEN) / 128);
    out_wmma_kernel<<<ggrid, 256, OUT_SMEM>>>(bo, out);
}

// round 10
// speedup vs baseline: 1.0606x; 1.0606x over previous
#include <cuda_runtime.h>
#include <cuda_bf16.h>
#include <mma.h>
#include <cstdint>

using namespace nvcuda;

#define N_B    4
#define S_LEN  2048
#define EMB    1024
#define HEADS  16
#define HD     64
#define MWORDS (S_LEN / 32)

#define PT   72    // bf16 smem pitch (144 B rows)
#define PSCR 20

// ---------------- scratch (device globals) ---------------------------------
__device__ __nv_bfloat16 g_qh[N_B * HEADS * S_LEN * HD];
__device__ __nv_bfloat16 g_ql[N_B * HEADS * S_LEN * HD];
__device__ __nv_bfloat16 g_kh[N_B * HEADS * S_LEN * HD];
__device__ __nv_bfloat16 g_kl[N_B * HEADS * S_LEN * HD];
__device__ __nv_bfloat16 g_vh[N_B * HEADS * S_LEN * HD];
__device__ __nv_bfloat16 g_vl[N_B * HEADS * S_LEN * HD];
__device__ __nv_bfloat16 g_aoh[N_B * S_LEN * EMB];
__device__ __nv_bfloat16 g_aol[N_B * S_LEN * EMB];
__device__ __nv_bfloat16 g_woh[EMB * EMB];
__device__ __nv_bfloat16 g_wol[EMB * EMB];
__device__ unsigned g_mbits[N_B * S_LEN * MWORDS];

__device__ __forceinline__ void split2(float x0, float x1, uint32_t& hi, uint32_t& lo) {
    __nv_bfloat16 h0 = __float2bfloat16_rn(x0), h1 = __float2bfloat16_rn(x1);
    float r0 = x0 - __bfloat162float(h0), r1 = x1 - __bfloat162float(h1);
    __nv_bfloat16 l0 = __float2bfloat16_rn(r0), l1 = __float2bfloat16_rn(r1);
    __nv_bfloat162 hp; hp.x = h0; hp.y = h1;
    __nv_bfloat162 lp; lp.x = l0; lp.y = l1;
    hi = *reinterpret_cast<uint32_t*>(&hp);
    lo = *reinterpret_cast<uint32_t*>(&lp);
}

__device__ __forceinline__ uint32_t smem_u32(const void* p) {
    uint32_t a;
    asm("{ .reg .u64 t; cvta.to.shared.u64 t, %1; cvt.u32.u64 %0, t; }"
        : "=r"(a) : "l"(p));
    return a;
}

// ---- tensor-core / async-copy primitives ----------------------------------
__device__ __forceinline__ void ldsm_x4(uint32_t* r, uint32_t addr) {
    asm volatile("ldmatrix.sync.aligned.m8n8.x4.shared.b16 {%0,%1,%2,%3}, [%4];"
                 : "=r"(r[0]), "=r"(r[1]), "=r"(r[2]), "=r"(r[3]) : "r"(addr));
}
__device__ __forceinline__ void ldsm_x4_t(uint32_t* r, uint32_t addr) {
    asm volatile("ldmatrix.sync.aligned.m8n8.x4.trans.shared.b16 {%0,%1,%2,%3}, [%4];"
                 : "=r"(r[0]), "=r"(r[1]), "=r"(r[2]), "=r"(r[3]) : "r"(addr));
}
__device__ __forceinline__ void mma16816(float* d, const uint32_t* a, const uint32_t* b) {
    asm volatile(
        "mma.sync.aligned.m16n8k16.row.col.f32.bf16.bf16.f32 "
        "{%0,%1,%2,%3}, {%4,%5,%6,%7}, {%8,%9}, {%0,%1,%2,%3};"
        : "+f"(d[0]), "+f"(d[1]), "+f"(d[2]), "+f"(d[3])
        : "r"(a[0]), "r"(a[1]), "r"(a[2]), "r"(a[3]), "r"(b[0]), "r"(b[1]));
}
__device__ __forceinline__ void cp16(uint32_t dst, const void* src) {
    asm volatile("cp.async.cg.shared.global [%0], [%1], 16;" :: "r"(dst), "l"(src));
}
#define CP_COMMIT() asm volatile("cp.async.commit_group;" ::: "memory")
#define CP_WAIT0()  asm volatile("cp.async.wait_group 0;" ::: "memory")

// stage nrows x 64 f32 -> bf16 hi/lo smem pitch PT (proj only)
__device__ __forceinline__ void stage_rows_f32(const float* __restrict__ src, size_t stride,
                                               char* s_hi, char* s_lo, int t)
{
    const int r    = t >> 1;
    const int half = t & 1;
    const float4* s4 = (const float4*)(src + (size_t)r * stride) + half * 8;
#pragma unroll
    for (int tt = 0; tt < 4; tt++) {
        float4 a = s4[2 * tt], b = s4[2 * tt + 1];
        float f[8] = {a.x, a.y, a.z, a.w, b.x, b.y, b.z, b.w};
        uint32_t H[4], L[4];
#pragma unroll
        for (int u = 0; u < 4; u++) split2(f[2 * u], f[2 * u + 1], H[u], L[u]);
        uint32_t off = (uint32_t)(r * (PT * 2) + half * 64 + tt * 16);
        *(uint4*)(s_hi + off) = make_uint4(H[0], H[1], H[2], H[3]);
        *(uint4*)(s_lo + off) = make_uint4(L[0], L[1], L[2], L[3]);
    }
}

// ---------------------------------------------------------------------------
// Kernel 0a: pack mask bits
// ---------------------------------------------------------------------------
__global__ __launch_bounds__(256)
void mask_pack_kernel(const int* __restrict__ mask)
{
    int gid  = blockIdx.x * 256 + threadIdx.x;
    int w    = gid >> 5;
    int lane = gid & 31;
    int v = mask[(size_t)w * 32 + lane];
    unsigned bits = __ballot_sync(0xffffffffu, v != 0);
    if (lane == 0) g_mbits[w] = bits;
}

// ---------------------------------------------------------------------------
// Kernel 0b: pre-split Wo (once)
// ---------------------------------------------------------------------------
__global__ __launch_bounds__(256)
void wo_split_kernel(const float* __restrict__ Wo)
{
    size_t idx = ((size_t)blockIdx.x * 256 + threadIdx.x) * 8;
    float4 a = *(const float4*)(Wo + idx);
    float4 b = *(const float4*)(Wo + idx + 4);
    float f[8] = {a.x, a.y, a.z, a.w, b.x, b.y, b.z, b.w};
    uint32_t H[4], L[4];
#pragma unroll
    for (int u = 0; u < 4; u++) split2(f[2 * u], f[2 * u + 1], H[u], L[u]);
    *(uint4*)(g_woh + idx) = make_uint4(H[0], H[1], H[2], H[3]);
    *(uint4*)(g_wol + idx) = make_uint4(L[0], L[1], L[2], L[3]);
}

// ---------------------------------------------------------------------------
// Kernel 1: projections — Q pre-scaled by 1/32 (exact) in the epilogue
// ---------------------------------------------------------------------------
#define PJ_WHI 0
#define PJ_WLO 9216
#define PJ_XHI 18432
#define PJ_XLO 36864
#define PJ_SCR 55296
#define PJ_SMEM (55296 + 10240)

__global__ __launch_bounds__(256, 2)
void proj_wmma_kernel(const float* __restrict__ xq, const float* __restrict__ xk,
                      const float* __restrict__ xv,
                      const float* __restrict__ Wq, const float* __restrict__ Wk,
                      const float* __restrict__ Wv)
{
    extern __shared__ char sm[];
    __nv_bfloat16* Whi = (__nv_bfloat16*)(sm + PJ_WHI);
    __nv_bfloat16* Wlo = (__nv_bfloat16*)(sm + PJ_WLO);
    __nv_bfloat16* Xhi = (__nv_bfloat16*)(sm + PJ_XHI);
    __nv_bfloat16* Xlo = (__nv_bfloat16*)(sm + PJ_XLO);

    const int which = blockIdx.z;
    const float* X; const float* W; __nv_bfloat16* Yh; __nv_bfloat16* Yl;
    if (which == 0)      { X = xq; W = Wq; Yh = g_qh; Yl = g_ql; }
    else if (which == 1) { X = xk; W = Wk; Yh = g_kh; Yl = g_kl; }
    else                 { X = xv; W = Wv; Yh = g_vh; Yl = g_vl; }
    const float oscale = (which == 0) ? 0.03125f : 1.0f;   // fold 1/sqrt(EMB) into Q

    const int nh = blockIdx.y;
    const int n  = nh / HEADS;
    const int h  = nh % HEADS;
    const int s0 = blockIdx.x * 128;
    const int tid = threadIdx.x, wid = tid >> 5, lane = tid & 31;
    float* scr = (float*)(sm + PJ_SCR) + wid * (16 * PSCR);

    stage_rows_f32(X + (size_t)(n * S_LEN + s0) * EMB + h * HD, EMB,
                   (char*)Xhi, (char*)Xlo, tid);
    if (tid < 128)
        stage_rows_f32(W, HD, (char*)Whi, (char*)Wlo, tid);
    __syncthreads();

    wmma::fragment<wmma::accumulator, 16, 16, 16, float> acc[4];
#pragma unroll
    for (int j = 0; j < 4; j++) wmma::fill_fragment(acc[j], 0.0f);

#pragma unroll
    for (int kk = 0; kk < 4; kk++) {
        wmma::fragment<wmma::matrix_a, 16, 16, 16, __nv_bfloat16, wmma::row_major> ah, al;
        wmma::load_matrix_sync(ah, Xhi + wid * 16 * PT + kk * 16, PT);
        wmma::load_matrix_sync(al, Xlo + wid * 16 * PT + kk * 16, PT);
#pragma unroll
        for (int j = 0; j < 4; j++) {
            wmma::fragment<wmma::matrix_b, 16, 16, 16, __nv_bfloat16, wmma::col_major> bh, bl;
            wmma::load_matrix_sync(bh, Whi + j * 16 * PT + kk * 16, PT);
            wmma::load_matrix_sync(bl, Wlo + j * 16 * PT + kk * 16, PT);
            wmma::mma_sync(acc[j], ah, bh, acc[j]);
            wmma::mma_sync(acc[j], ah, bl, acc[j]);
            wmma::mma_sync(acc[j], al, bh, acc[j]);
        }
    }

    const int r = lane >> 1, cw = lane & 1;
    const size_t ybase = (size_t)((n * HEADS + h) * S_LEN + s0 + wid * 16) * HD;
#pragma unroll
    for (int j = 0; j < 4; j++) {
        wmma::store_matrix_sync(scr, acc[j], PSCR, wmma::mem_row_major);
        __syncwarp();
        const float* s = scr + r * PSCR + cw * 8;
        uint32_t H[4], L[4];
#pragma unroll
        for (int u = 0; u < 4; u++)
            split2(s[2 * u] * oscale, s[2 * u + 1] * oscale, H[u], L[u]);
        const size_t off = ybase + (size_t)r * HD + j * 16 + cw * 8;
        *(uint4*)(Yh + off) = make_uint4(H[0], H[1], H[2], H[3]);
        *(uint4*)(Yl + off) = make_uint4(L[0], L[1], L[2], L[3]);
        __syncwarp();
    }
}

// ---------------------------------------------------------------------------
// Kernel 2: flash attention — kv-tile 64 (2 register-softmax halves per tile)
// grid (HEADS, S_LEN/128, N_B), 256 threads
// smem: Q 36864 + 2 KV stages of 36864 (Kh 0 / Kl 9216 / Vh 18432 / Vl 27648)
// ---------------------------------------------------------------------------
#define A_QHI  0
#define A_QLO  18432
#define A_RING 36864
#define KV_STG 36864
#define KV_KLO 9216
#define KV_VHI 18432
#define KV_VLO 27648
#define ATTN_SMEM (36864 + 2 * 36864 + 256)
#define NIT2 (S_LEN / 64)

__global__ __launch_bounds__(256, 2)
void attn_mma_kernel()
{
    extern __shared__ char sm[];
    const int tid = threadIdx.x, wid = tid >> 5, lane = tid & 31;
    const int h = blockIdx.x, qt = blockIdx.y, n = blockIdx.z;
    const int q0 = qt * 128;

    const size_t head_base = (size_t)(n * HEADS + h) * S_LEN * HD;
    const __nv_bfloat16* Qh = g_qh + head_base + (size_t)q0 * HD;
    const __nv_bfloat16* Ql = g_ql + head_base + (size_t)q0 * HD;
    const __nv_bfloat16* Kh = g_kh + head_base;
    const __nv_bfloat16* Kl = g_kl + head_base;
    const __nv_bfloat16* Vh = g_vh + head_base;
    const __nv_bfloat16* Vl = g_vl + head_base;

    const uint32_t smb = smem_u32(sm);

    // staging map: per 64-row tile, thread covers chunks tid and tid+256
    const int r0c = tid >> 3,         oct0 = tid & 7;          // chunk 0
    const int r1c = (tid + 256) >> 3, oct1 = tid & 7;          // chunk 1 (rows 32..63)
    const uint32_t so0 = (uint32_t)(r0c * (PT * 2) + oct0 * 16);
    const uint32_t so1 = (uint32_t)(r1c * (PT * 2) + oct1 * 16);

    // ---- prologue: prefetch KV tile 0 into stage 0 ----
    {
        const size_t g0 = (size_t)r0c * HD + oct0 * 8;
        const size_t g1 = (size_t)r1c * HD + oct1 * 8;
        const uint32_t d = smb + A_RING;
        cp16(d + so0,          Kh + g0);  cp16(d + so1,          Kh + g1);
        cp16(d + KV_KLO + so0, Kl + g0);  cp16(d + KV_KLO + so1, Kl + g1);
        cp16(d + KV_VHI + so0, Vh + g0);  cp16(d + KV_VHI + so1, Vh + g1);
        cp16(d + KV_VLO + so0, Vl + g0);  cp16(d + KV_VLO + so1, Vl + g1);
    }
    CP_COMMIT();

    // ---- stage Q, hoist fragments ----
    {
        const int r = tid >> 1, half = tid & 1;
        const char* sh0 = (const char*)(Qh + (size_t)r * HD + half * 32);
        const char* sl0 = (const char*)(Ql + (size_t)r * HD + half * 32);
        uint32_t off = (uint32_t)(r * (PT * 2) + half * 64);
#pragma unroll
        for (int tt = 0; tt < 4; tt++) {
            *(uint4*)(sm + A_QHI + off + tt * 16) = *(const uint4*)(sh0 + tt * 16);
            *(uint4*)(sm + A_QLO + off + tt * 16) = *(const uint4*)(sl0 + tt * 16);
        }
    }
    __syncthreads();

    const int l7  = lane & 7;
    const int s01 = (lane >> 3) & 1;
    const int s23 = (lane >> 4) & 1;

    uint32_t qh[4][4], ql[4][4];
    {
        uint32_t base = smb + (uint32_t)((wid * 16 + l7 + s01 * 8) * (PT * 2)) + s23 * 16;
#pragma unroll
        for (int c = 0; c < 4; c++) {
            ldsm_x4(qh[c], base + A_QHI + c * 32);
            ldsm_x4(ql[c], base + A_QLO + c * 32);
        }
    }

    const int g   = lane >> 2;
    const int tig = lane & 3;
    const int qrow_g  = q0 + wid * 16 + g;
    const unsigned* mrow0 = g_mbits + (size_t)(n * S_LEN + qrow_g) * MWORDS;
    const unsigned* mrow8 = mrow0 + 8 * MWORDS;

    const uint32_t kqoff = (uint32_t)(((lane >> 4) * 8 + l7) * (PT * 2)) + ((lane >> 3) & 1) * 16;
    const uint32_t voff  = (uint32_t)((((lane >> 3) & 1) * 8 + l7) * (PT * 2)) + (lane >> 4) * 16;

    float o[8][4];
#pragma unroll
    for (int j = 0; j < 8; j++)
#pragma unroll
        for (int u = 0; u < 4; u++) o[j][u] = 0.f;
    float lsum_g = 0.f, lsum_8 = 0.f;

    for (int it = 0; it < NIT2; it++) {
        const uint32_t kv = smb + A_RING + (it & 1) * KV_STG;

        CP_WAIT0();
        __syncthreads();

        // prefetch tile it+1 into the other stage
        if (it + 1 < NIT2) {
            const size_t tb = (size_t)(it + 1) * 64 * HD;
            const size_t g0 = tb + (size_t)r0c * HD + oct0 * 8;
            const size_t g1 = tb + (size_t)r1c * HD + oct1 * 8;
            const uint32_t d = smb + A_RING + ((it + 1) & 1) * KV_STG;
            cp16(d + so0,          Kh + g0);  cp16(d + so1,          Kh + g1);
            cp16(d + KV_KLO + so0, Kl + g0);  cp16(d + KV_KLO + so1, Kl + g1);
            cp16(d + KV_VHI + so0, Vh + g0);  cp16(d + KV_VHI + so1, Vh + g1);
            cp16(d + KV_VLO + so0, Vl + g0);  cp16(d + KV_VLO + so1, Vl + g1);
        }
        CP_COMMIT();

        // ---- two 32-col half-passes over this 64-kv tile ----
#pragma unroll
        for (int h2 = 0; h2 < 2; h2++) {
            const uint32_t kvh = kv + (uint32_t)(h2 * 32 * (PT * 2));

            // S = Q K^T
            float s[4][4];
#pragma unroll
            for (int j = 0; j < 4; j++)
#pragma unroll
                for (int u = 0; u < 4; u++) s[j][u] = 0.f;

#pragma unroll
            for (int c = 0; c < 4; c++) {
                uint32_t bh0[4], bl0[4], bh1[4], bl1[4];
                const uint32_t ka0 = kvh + kqoff + c * 32;
                const uint32_t ka1 = ka0 + (uint32_t)(16 * (PT * 2));
                ldsm_x4(bh0, ka0); ldsm_x4(bl0, ka0 + KV_KLO);
                ldsm_x4(bh1, ka1); ldsm_x4(bl1, ka1 + KV_KLO);
                mma16816(s[0], qh[c], bh0); mma16816(s[1], qh[c], bh0 + 2);
                mma16816(s[2], qh[c], bh1); mma16816(s[3], qh[c], bh1 + 2);
                mma16816(s[0], qh[c], bl0); mma16816(s[1], qh[c], bl0 + 2);
                mma16816(s[2], qh[c], bl1); mma16816(s[3], qh[c], bl1 + 2);
                mma16816(s[0], ql[c], bh0); mma16816(s[1], ql[c], bh0 + 2);
                mma16816(s[2], ql[c], bh1); mma16816(s[3], ql[c], bh1 + 2);
            }

            // softmax in registers (Q pre-scaled; no SC multiply)
            const unsigned w0 = mrow0[it * 2 + h2];
            const unsigned w8 = mrow8[it * 2 + h2];
#pragma unroll
            for (int j = 0; j < 4; j++) {
                const int bit = j * 8 + tig * 2;
                float p0 = __expf(s[j][0]);
                float p1 = __expf(s[j][1]);
                float p2 = __expf(s[j][2]);
                float p3 = __expf(s[j][3]);
                p0 = ((w0 >> bit) & 1u)       ? p0 : 0.f;
                p1 = ((w0 >> (bit + 1)) & 1u) ? p1 : 0.f;
                p2 = ((w8 >> bit) & 1u)       ? p2 : 0.f;
                p3 = ((w8 >> (bit + 1)) & 1u) ? p3 : 0.f;
                lsum_g += p0 + p1;
                lsum_8 += p2 + p3;
                s[j][0] = p0; s[j][1] = p1; s[j][2] = p2; s[j][3] = p3;
            }

            // O += P V
#pragma unroll
            for (int c2 = 0; c2 < 2; c2++) {
                uint32_t ah[4], al[4];
                split2(s[2 * c2][0],     s[2 * c2][1],     ah[0], al[0]);
                split2(s[2 * c2][2],     s[2 * c2][3],     ah[1], al[1]);
                split2(s[2 * c2 + 1][0], s[2 * c2 + 1][1], ah[2], al[2]);
                split2(s[2 * c2 + 1][2], s[2 * c2 + 1][3], ah[3], al[3]);
#pragma unroll
                for (int jpp = 0; jpp < 2; jpp++) {
                    uint32_t bh0[4], bl0[4], bh1[4], bl1[4];
                    const uint32_t va0 = kv + KV_VHI + voff +
                        (uint32_t)((h2 * 32 + c2 * 16) * (PT * 2)) + jpp * 64;
                    const uint32_t va1 = va0 + 32;
                    ldsm_x4_t(bh0, va0); ldsm_x4_t(bl0, va0 + (KV_VLO - KV_VHI));
                    ldsm_x4_t(bh1, va1); ldsm_x4_t(bl1, va1 + (KV_VLO - KV_VHI));
                    float* o0 = o[4 * jpp + 0];
                    float* o1 = o[4 * jpp + 1];
                    float* o2 = o[4 * jpp + 2];
                    float* o3 = o[4 * jpp + 3];
                    mma16816(o0, ah, bh0); mma16816(o1, ah, bh0 + 2);
                    mma16816(o2, ah, bh1); mma16816(o3, ah, bh1 + 2);
                    mma16816(o0, ah, bl0); mma16816(o1, ah, bl0 + 2);
                    mma16816(o2, ah, bl1); mma16816(o3, ah, bl1 + 2);
                    mma16816(o0, al, bh0); mma16816(o1, al, bh0 + 2);
                    mma16816(o2, al, bh1); mma16816(o3, al, bh1 + 2);
                }
            }
        }
    }

    // ---- epilogue ----
    lsum_g += __shfl_xor_sync(0xffffffffu, lsum_g, 1);
    lsum_g += __shfl_xor_sync(0xffffffffu, lsum_g, 2);
    lsum_8 += __shfl_xor_sync(0xffffffffu, lsum_8, 1);
    lsum_8 += __shfl_xor_sync(0xffffffffu, lsum_8, 2);
    const float inv_g = 1.0f / lsum_g;
    const float inv_8 = 1.0f / lsum_8;

    const size_t d0 = (size_t)(n * S_LEN + qrow_g) * EMB + h * HD;
    const size_t d8 = d0 + (size_t)8 * EMB;
#pragma unroll
    for (int j = 0; j < 8; j++) {
        const int col = j * 8 + tig * 2;
        uint32_t H, L;
        split2(o[j][0] * inv_g, o[j][1] * inv_g, H, L);
        *(uint32_t*)(g_aoh + d0 + col) = H;
        *(uint32_t*)(g_aol + d0 + col) = L;
        split2(o[j][2] * inv_8, o[j][3] * inv_8, H, L);
        *(uint32_t*)(g_aoh + d8 + col) = H;
        *(uint32_t*)(g_aol + d8 + col) = L;
    }
}

// ---------------------------------------------------------------------------
// Kernel 3: output projection — raw mma.sync, BK=32, 2-stage cp.async ring
// grid (EMB/128, 8192/128), 256 threads. CTA 128x128, warp 32x64.
// stage: Ahi 0 / Alo 10240 / Bhi 20480 / Blo 30720 (pitch 40 bf16 = 80 B rows)
// ---------------------------------------------------------------------------
#define OPKB    80          // bytes per staged row (40 bf16)
#define OB2_SZ  40960
#define OB2_ALO 10240
#define OB2_BHI 20480
#define OB2_BLO 30720
#define OUT2_SMEM (2 * 40960 + 128)
#define ONIT2 (EMB / 32)

__global__ __launch_bounds__(256, 2)
void out_mma_kernel(const float* __restrict__ bo, float* __restrict__ out)
{
    extern __shared__ char sm[];
    const uint32_t smb = smem_u32(sm);

    const int tid = threadIdx.x, wid = tid >> 5, lane = tid & 31;
    const int r0 = blockIdx.y * 128;
    const int e0 = blockIdx.x * 128;
    const int wr = wid & 3;     // 32-row band
    const int wc = wid >> 2;    // 64-col band

    const int l7  = lane & 7;
    const int s01 = (lane >> 3) & 1;
    const int s23 = lane >> 4;
    const uint32_t aoff = (uint32_t)((l7 + s01 * 8) * OPKB) + s23 * 16;
    const uint32_t boff = (uint32_t)((s23 * 8 + l7) * OPKB) + s01 * 16;

    float acc[2][8][4];
#pragma unroll
    for (int m = 0; m < 2; m++)
#pragma unroll
        for (int j = 0; j < 8; j++)
#pragma unroll
            for (int u = 0; u < 4; u++) acc[m][j][u] = 0.f;

    // staging: thread covers chunks tid and tid+256; chunk c -> row c>>2, quarter c&3
    const int ar0 = tid >> 2,          aq0 = tid & 3;
    const int ar1 = (tid + 256) >> 2,  aq1 = tid & 3;
    const uint32_t os0 = (uint32_t)(ar0 * OPKB + aq0 * 16);
    const uint32_t os1 = (uint32_t)(ar1 * OPKB + aq1 * 16);
    const size_t ag0 = (size_t)(r0 + ar0) * EMB + aq0 * 8;
    const size_t ag1 = (size_t)(r0 + ar1) * EMB + aq1 * 8;
    const size_t bg0 = (size_t)(e0 + ar0) * EMB + aq0 * 8;
    const size_t bg1 = (size_t)(e0 + ar1) * EMB + aq1 * 8;

    // prologue: prefetch stage 0 (k-cols 0..31)
    {
        const uint32_t d = smb;
        cp16(d + os0,           g_aoh + ag0);  cp16(d + os1,           g_aoh + ag1);
        cp16(d + OB2_ALO + os0, g_aol + ag0);  cp16(d + OB2_ALO + os1, g_aol + ag1);
        cp16(d + OB2_BHI + os0, g_woh + bg0);  cp16(d + OB2_BHI + os1, g_woh + bg1);
        cp16(d + OB2_BLO + os0, g_wol + bg0);  cp16(d + OB2_BLO + os1, g_wol + bg1);
    }
    CP_COMMIT();

    for (int ic = 0; ic < ONIT2; ic++) {
        const uint32_t buf = smb + (ic & 1) * OB2_SZ;

        CP_WAIT0();
        __syncthreads();

        if (ic + 1 < ONIT2) {
            const int c1 = (ic + 1) * 32;
            const uint32_t d = smb + ((ic + 1) & 1) * OB2_SZ;
            cp16(d + os0,           g_aoh + ag0 + c1);  cp16(d + os1,           g_aoh + ag1 + c1);
            cp16(d + OB2_ALO + os0, g_aol + ag0 + c1);  cp16(d + OB2_ALO + os1, g_aol + ag1 + c1);
            cp16(d + OB2_BHI + os0, g_woh + bg0 + c1);  cp16(d + OB2_BHI + os1, g_woh + bg1 + c1);
            cp16(d + OB2_BLO + os0, g_wol + bg0 + c1);  cp16(d + OB2_BLO + os1, g_wol + bg1 + c1);
        }
        CP_COMMIT();

#pragma unroll
        for (int kk = 0; kk < 2; kk++) {
            uint32_t ah0[4], al0[4], ah1[4], al1[4];
            const uint32_t aa0 = buf + (uint32_t)(wr * 32 * OPKB) + aoff + kk * 32;
            const uint32_t aa1 = aa0 + (uint32_t)(16 * OPKB);
            ldsm_x4(ah0, aa0); ldsm_x4(al0, aa0 + OB2_ALO);
            ldsm_x4(ah1, aa1); ldsm_x4(al1, aa1 + OB2_ALO);
#pragma unroll
            for (int jj = 0; jj < 4; jj++) {
                uint32_t bh[4], bl[4];
                const uint32_t ba = buf + OB2_BHI +
                    (uint32_t)((wc * 64 + jj * 16) * OPKB) + boff + kk * 32;
                ldsm_x4(bh, ba); ldsm_x4(bl, ba + (OB2_BLO - OB2_BHI));
                mma16816(acc[0][2 * jj],     ah0, bh); mma16816(acc[0][2 * jj + 1], ah0, bh + 2);
                mma16816(acc[1][2 * jj],     ah1, bh); mma16816(acc[1][2 * jj + 1], ah1, bh + 2);
                mma16816(acc[0][2 * jj],     ah0, bl); mma16816(acc[0][2 * jj + 1], ah0, bl + 2);
                mma16816(acc[1][2 * jj],     ah1, bl); mma16816(acc[1][2 * jj + 1], ah1, bl + 2);
                mma16816(acc[0][2 * jj],     al0, bh); mma16816(acc[0][2 * jj + 1], al0, bh + 2);
                mma16816(acc[1][2 * jj],     al1, bh); mma16816(acc[1][2 * jj + 1], al1, bh + 2);
            }
        }
    }

    // epilogue: + bias, direct stores (no smem round-trip)
    const int g   = lane >> 2;
    const int tig = lane & 3;
#pragma unroll
    for (int m = 0; m < 2; m++) {
        const int row  = r0 + wr * 32 + m * 16 + g;
        const int row8 = row + 8;
#pragma unroll
        for (int jn = 0; jn < 8; jn++) {
            const int col = e0 + wc * 64 + jn * 8 + tig * 2;
            const float2 bb = *(const float2*)(bo + col);
            float2 v0 = make_float2(acc[m][jn][0] + bb.x, acc[m][jn][1] + bb.y);
            float2 v1 = make_float2(acc[m][jn][2] + bb.x, acc[m][jn][3] + bb.y);
            *(float2*)(out + (size_t)row  * EMB + col) = v0;
            *(float2*)(out + (size_t)row8 * EMB + col) = v1;
        }
    }
}

// ---------------------------------------------------------------------------
extern "C" void kernel_launch(void* const* d_in, const int* in_sizes, int n_in,
                              void* d_out, int out_size)
{
    const float* values  = (const float*)d_in[0];
    const float* queries = (const float*)d_in[1];
    const float* keys    = (const float*)d_in[2];
    const int*   mask    = (const int*)  d_in[3];
    const float* Wv      = (const float*)d_in[4];
    const float* Wk      = (const float*)d_in[5];
    const float* Wq      = (const float*)d_in[6];
    const float* Wo      = (const float*)d_in[7];
    const float* bo      = (const float*)d_in[8];
    float* out = (float*)d_out;

    static bool attr_set = false;
    if (!attr_set) {
        cudaFuncSetAttribute(proj_wmma_kernel,
                             cudaFuncAttributeMaxDynamicSharedMemorySize, PJ_SMEM);
        cudaFuncSetAttribute(attn_mma_kernel,
                             cudaFuncAttributeMaxDynamicSharedMemorySize, ATTN_SMEM);
        cudaFuncSetAttribute(out_mma_kernel,
                             cudaFuncAttributeMaxDynamicSharedMemorySize, OUT2_SMEM);
        attr_set = true;
    }

    mask_pack_kernel<<<(N_B * S_LEN * MWORDS * 32) / 256, 256>>>(mask);
    wo_split_kernel<<<(EMB * EMB) / (256 * 8), 256>>>(Wo);

    dim3 pgrid(S_LEN / 128, N_B * HEADS, 3);
    proj_wmma_kernel<<<pgrid, 256, PJ_SMEM>>>(queries, keys, values, Wq, Wk, Wv);

    dim3 agrid(HEADS, S_LEN / 128, N_B);
    attn_mma_kernel<<<agrid, 256, ATTN_SMEM>>>();

    dim3 ggrid(EMB / 128, (N_B * S_LEN) / 128);
    out_mma_kernel<<<ggrid, 256, OUT2_SMEM>>>(bo, out);
}

// round 11
// speedup vs baseline: 1.3125x; 1.2375x over previous
#include <cuda_runtime.h>
#include <cuda_fp16.h>
#include <mma.h>
#include <cstdint>

using namespace nvcuda;

#define N_B    4
#define S_LEN  2048
#define EMB    1024
#define HEADS  16
#define HD     64
#define MWORDS (S_LEN / 32)

#define PT   72    // fp16 smem pitch (144 B rows)
#define PSCR 20

// ---------------- scratch (device globals) ---------------------------------
__device__ __half g_qh[N_B * HEADS * S_LEN * HD];
__device__ __half g_ql[N_B * HEADS * S_LEN * HD];
__device__ __half g_kh[N_B * HEADS * S_LEN * HD];
__device__ __half g_kl[N_B * HEADS * S_LEN * HD];
__device__ __half g_vh[N_B * HEADS * S_LEN * HD];
__device__ __half g_vl[N_B * HEADS * S_LEN * HD];
__device__ __half g_ao[N_B * S_LEN * EMB];          // single fp16
__device__ __half g_woh[EMB * EMB];
__device__ __half g_wol[EMB * EMB];
__device__ unsigned g_mbits[N_B * S_LEN * MWORDS];

__device__ __forceinline__ uint32_t pack2h(float a, float b) {
    __half2 h = __floats2half2_rn(a, b);
    return *reinterpret_cast<uint32_t*>(&h);
}
__device__ __forceinline__ void split2h(float x0, float x1, uint32_t& hi, uint32_t& lo) {
    __half h0 = __float2half_rn(x0), h1 = __float2half_rn(x1);
    float r0 = x0 - __half2float(h0), r1 = x1 - __half2float(h1);
    __half l0 = __float2half_rn(r0), l1 = __float2half_rn(r1);
    __half2 hp; hp.x = h0; hp.y = h1;
    __half2 lp; lp.x = l0; lp.y = l1;
    hi = *reinterpret_cast<uint32_t*>(&hp);
    lo = *reinterpret_cast<uint32_t*>(&lp);
}

__device__ __forceinline__ uint32_t smem_u32(const void* p) {
    uint32_t a;
    asm("{ .reg .u64 t; cvta.to.shared.u64 t, %1; cvt.u32.u64 %0, t; }"
        : "=r"(a) : "l"(p));
    return a;
}

// ---- tensor-core / async-copy primitives ----------------------------------
__device__ __forceinline__ void ldsm_x4(uint32_t* r, uint32_t addr) {
    asm volatile("ldmatrix.sync.aligned.m8n8.x4.shared.b16 {%0,%1,%2,%3}, [%4];"
                 : "=r"(r[0]), "=r"(r[1]), "=r"(r[2]), "=r"(r[3]) : "r"(addr));
}
__device__ __forceinline__ void ldsm_x4_t(uint32_t* r, uint32_t addr) {
    asm volatile("ldmatrix.sync.aligned.m8n8.x4.trans.shared.b16 {%0,%1,%2,%3}, [%4];"
                 : "=r"(r[0]), "=r"(r[1]), "=r"(r[2]), "=r"(r[3]) : "r"(addr));
}
__device__ __forceinline__ void mma16816(float* d, const uint32_t* a, const uint32_t* b) {
    asm volatile(
        "mma.sync.aligned.m16n8k16.row.col.f32.f16.f16.f32 "
        "{%0,%1,%2,%3}, {%4,%5,%6,%7}, {%8,%9}, {%0,%1,%2,%3};"
        : "+f"(d[0]), "+f"(d[1]), "+f"(d[2]), "+f"(d[3])
        : "r"(a[0]), "r"(a[1]), "r"(a[2]), "r"(a[3]), "r"(b[0]), "r"(b[1]));
}
__device__ __forceinline__ void cp16(uint32_t dst, const void* src) {
    asm volatile("cp.async.cg.shared.global [%0], [%1], 16;" :: "r"(dst), "l"(src));
}
#define CP_COMMIT() asm volatile("cp.async.commit_group;" ::: "memory")
#define CP_WAIT0()  asm volatile("cp.async.wait_group 0;" ::: "memory")

// stage nrows x 64 f32 -> fp16 hi/lo smem pitch PT (proj only)
__device__ __forceinline__ void stage_rows_f32(const float* __restrict__ src, size_t stride,
                                               char* s_hi, char* s_lo, int t)
{
    const int r    = t >> 1;
    const int half = t & 1;
    const float4* s4 = (const float4*)(src + (size_t)r * stride) + half * 8;
#pragma unroll
    for (int tt = 0; tt < 4; tt++) {
        float4 a = s4[2 * tt], b = s4[2 * tt + 1];
        float f[8] = {a.x, a.y, a.z, a.w, b.x, b.y, b.z, b.w};
        uint32_t H[4], L[4];
#pragma unroll
        for (int u = 0; u < 4; u++) split2h(f[2 * u], f[2 * u + 1], H[u], L[u]);
        uint32_t off = (uint32_t)(r * (PT * 2) + half * 64 + tt * 16);
        *(uint4*)(s_hi + off) = make_uint4(H[0], H[1], H[2], H[3]);
        *(uint4*)(s_lo + off) = make_uint4(L[0], L[1], L[2], L[3]);
    }
}

// ---------------------------------------------------------------------------
// Kernel 0a: pack mask bits
// ---------------------------------------------------------------------------
__global__ __launch_bounds__(256)
void mask_pack_kernel(const int* __restrict__ mask)
{
    int gid  = blockIdx.x * 256 + threadIdx.x;
    int w    = gid >> 5;
    int lane = gid & 31;
    int v = mask[(size_t)w * 32 + lane];
    unsigned bits = __ballot_sync(0xffffffffu, v != 0);
    if (lane == 0) g_mbits[w] = bits;
}

// ---------------------------------------------------------------------------
// Kernel 0b: pre-split Wo into fp16 hi/lo
// ---------------------------------------------------------------------------
__global__ __launch_bounds__(256)
void wo_split_kernel(const float* __restrict__ Wo)
{
    size_t idx = ((size_t)blockIdx.x * 256 + threadIdx.x) * 8;
    float4 a = *(const float4*)(Wo + idx);
    float4 b = *(const float4*)(Wo + idx + 4);
    float f[8] = {a.x, a.y, a.z, a.w, b.x, b.y, b.z, b.w};
    uint32_t H[4], L[4];
#pragma unroll
    for (int u = 0; u < 4; u++) split2h(f[2 * u], f[2 * u + 1], H[u], L[u]);
    *(uint4*)(g_woh + idx) = make_uint4(H[0], H[1], H[2], H[3]);
    *(uint4*)(g_wol + idx) = make_uint4(L[0], L[1], L[2], L[3]);
}

// ---------------------------------------------------------------------------
// Kernel 1: projections via wmma fp16 3-term; outputs hi/lo fp16 (unscaled)
// ---------------------------------------------------------------------------
#define PJ_WHI 0
#define PJ_WLO 9216
#define PJ_XHI 18432
#define PJ_XLO 36864
#define PJ_SCR 55296
#define PJ_SMEM (55296 + 10240)

__global__ __launch_bounds__(256, 2)
void proj_wmma_kernel(const float* __restrict__ xq, const float* __restrict__ xk,
                      const float* __restrict__ xv,
                      const float* __restrict__ Wq, const float* __restrict__ Wk,
                      const float* __restrict__ Wv)
{
    extern __shared__ char sm[];
    __half* Whi = (__half*)(sm + PJ_WHI);
    __half* Wlo = (__half*)(sm + PJ_WLO);
    __half* Xhi = (__half*)(sm + PJ_XHI);
    __half* Xlo = (__half*)(sm + PJ_XLO);

    const int which = blockIdx.z;
    const float* X; const float* W; __half* Yh; __half* Yl;
    if (which == 0)      { X = xq; W = Wq; Yh = g_qh; Yl = g_ql; }
    else if (which == 1) { X = xk; W = Wk; Yh = g_kh; Yl = g_kl; }
    else                 { X = xv; W = Wv; Yh = g_vh; Yl = g_vl; }

    const int nh = blockIdx.y;
    const int n  = nh / HEADS;
    const int h  = nh % HEADS;
    const int s0 = blockIdx.x * 128;
    const int tid = threadIdx.x, wid = tid >> 5, lane = tid & 31;
    float* scr = (float*)(sm + PJ_SCR) + wid * (16 * PSCR);

    stage_rows_f32(X + (size_t)(n * S_LEN + s0) * EMB + h * HD, EMB,
                   (char*)Xhi, (char*)Xlo, tid);
    if (tid < 128)
        stage_rows_f32(W, HD, (char*)Whi, (char*)Wlo, tid);
    __syncthreads();

    wmma::fragment<wmma::accumulator, 16, 16, 16, float> acc[4];
#pragma unroll
    for (int j = 0; j < 4; j++) wmma::fill_fragment(acc[j], 0.0f);

#pragma unroll
    for (int kk = 0; kk < 4; kk++) {
        wmma::fragment<wmma::matrix_a, 16, 16, 16, __half, wmma::row_major> ah, al;
        wmma::load_matrix_sync(ah, Xhi + wid * 16 * PT + kk * 16, PT);
        wmma::load_matrix_sync(al, Xlo + wid * 16 * PT + kk * 16, PT);
#pragma unroll
        for (int j = 0; j < 4; j++) {
            wmma::fragment<wmma::matrix_b, 16, 16, 16, __half, wmma::col_major> bh, bl;
            wmma::load_matrix_sync(bh, Whi + j * 16 * PT + kk * 16, PT);
            wmma::load_matrix_sync(bl, Wlo + j * 16 * PT + kk * 16, PT);
            wmma::mma_sync(acc[j], ah, bh, acc[j]);
            wmma::mma_sync(acc[j], ah, bl, acc[j]);
            wmma::mma_sync(acc[j], al, bh, acc[j]);
        }
    }

    const int r = lane >> 1, cw = lane & 1;
    const size_t ybase = (size_t)((n * HEADS + h) * S_LEN + s0 + wid * 16) * HD;
#pragma unroll
    for (int j = 0; j < 4; j++) {
        wmma::store_matrix_sync(scr, acc[j], PSCR, wmma::mem_row_major);
        __syncwarp();
        const float* s = scr + r * PSCR + cw * 8;
        uint32_t H[4], L[4];
#pragma unroll
        for (int u = 0; u < 4; u++) split2h(s[2 * u], s[2 * u + 1], H[u], L[u]);
        const size_t off = ybase + (size_t)r * HD + j * 16 + cw * 8;
        *(uint4*)(Yh + off) = make_uint4(H[0], H[1], H[2], H[3]);
        *(uint4*)(Yl + off) = make_uint4(L[0], L[1], L[2], L[3]);
        __syncwarp();
    }
}

// ---------------------------------------------------------------------------
// Kernel 2: flash attention — fp16, QK 3-term, PV 2-term (P single fp16)
// grid (HEADS, S_LEN/128, N_B), 256 threads, kv-tile 32, 2-stage cp.async
// ---------------------------------------------------------------------------
#define A_QHI  0
#define A_QLO  18432
#define A_KV0  36864
#define A_KV1  55296
#define KV_KLO 4608
#define KV_VHI 9216
#define KV_VLO 13824
#define ATTN_SMEM (73728 + 256)
#define NIT (S_LEN / 32)

__global__ __launch_bounds__(256, 2)
void attn_mma_kernel()
{
    extern __shared__ char sm[];
    const int tid = threadIdx.x, wid = tid >> 5, lane = tid & 31;
    const int h = blockIdx.x, qt = blockIdx.y, n = blockIdx.z;
    const int q0 = qt * 128;

    const size_t head_base = (size_t)(n * HEADS + h) * S_LEN * HD;
    const __half* Qh = g_qh + head_base + (size_t)q0 * HD;
    const __half* Ql = g_ql + head_base + (size_t)q0 * HD;
    const __half* Kh = g_kh + head_base;
    const __half* Kl = g_kl + head_base;
    const __half* Vh = g_vh + head_base;
    const __half* Vl = g_vl + head_base;

    const uint32_t smb = smem_u32(sm);

    // ---- prefetch KV tile 0 ----
    const int str = tid >> 3, soct = tid & 7;
    const uint32_t soff = (uint32_t)(str * (PT * 2) + soct * 16);
    {
        const size_t gsrc = (size_t)str * HD + soct * 8;
        const uint32_t d = smb + A_KV0 + soff;
        cp16(d,           Kh + gsrc);
        cp16(d + KV_KLO,  Kl + gsrc);
        cp16(d + KV_VHI,  Vh + gsrc);
        cp16(d + KV_VLO,  Vl + gsrc);
    }
    CP_COMMIT();

    // ---- stage Q, hoist fragments ----
    {
        const int r = tid >> 1, half = tid & 1;
        const char* sh0 = (const char*)(Qh + (size_t)r * HD + half * 32);
        const char* sl0 = (const char*)(Ql + (size_t)r * HD + half * 32);
        uint32_t off = (uint32_t)(r * (PT * 2) + half * 64);
#pragma unroll
        for (int tt = 0; tt < 4; tt++) {
            *(uint4*)(sm + A_QHI + off + tt * 16) = *(const uint4*)(sh0 + tt * 16);
            *(uint4*)(sm + A_QLO + off + tt * 16) = *(const uint4*)(sl0 + tt * 16);
        }
    }
    __syncthreads();

    const int l7  = lane & 7;
    const int s01 = (lane >> 3) & 1;
    const int s23 = (lane >> 4) & 1;

    uint32_t qh[4][4], ql[4][4];
    {
        uint32_t base = smb + (uint32_t)((wid * 16 + l7 + s01 * 8) * (PT * 2)) + s23 * 16;
#pragma unroll
        for (int c = 0; c < 4; c++) {
            ldsm_x4(qh[c], base + A_QHI + c * 32);
            ldsm_x4(ql[c], base + A_QLO + c * 32);
        }
    }

    const int g   = lane >> 2;
    const int tig = lane & 3;
    const int qrow_g  = q0 + wid * 16 + g;
    const unsigned* mrow0 = g_mbits + (size_t)(n * S_LEN + qrow_g) * MWORDS;
    const unsigned* mrow8 = mrow0 + 8 * MWORDS;

    const uint32_t kqoff = (uint32_t)(((lane >> 4) * 8 + l7) * (PT * 2)) + ((lane >> 3) & 1) * 16;
    const uint32_t voff  = (uint32_t)((((lane >> 3) & 1) * 8 + l7) * (PT * 2)) + (lane >> 4) * 16;

    float o[8][4];
#pragma unroll
    for (int j = 0; j < 8; j++)
#pragma unroll
        for (int u = 0; u < 4; u++) o[j][u] = 0.f;
    float lsum_g = 0.f, lsum_8 = 0.f;

    const float SC = 0.03125f;

    for (int it = 0; it < NIT; it++) {
        const uint32_t kv = smb + ((it & 1) ? A_KV1 : A_KV0);

        CP_WAIT0();
        __syncthreads();

        if (it + 1 < NIT) {
            const size_t gsrc = (size_t)((it + 1) * 32 + str) * HD + soct * 8;
            const uint32_t d = smb + (((it + 1) & 1) ? A_KV1 : A_KV0) + soff;
            cp16(d,           Kh + gsrc);
            cp16(d + KV_KLO,  Kl + gsrc);
            cp16(d + KV_VHI,  Vh + gsrc);
            cp16(d + KV_VLO,  Vl + gsrc);
        }
        CP_COMMIT();

        // ---- S = Q K^T (3-term fp16) ----
        float s[4][4];
#pragma unroll
        for (int j = 0; j < 4; j++)
#pragma unroll
            for (int u = 0; u < 4; u++) s[j][u] = 0.f;

#pragma unroll
        for (int c = 0; c < 4; c++) {
            uint32_t bh0[4], bl0[4], bh1[4], bl1[4];
            const uint32_t ka0 = kv + kqoff + c * 32;
            const uint32_t ka1 = ka0 + (uint32_t)(16 * (PT * 2));
            ldsm_x4(bh0, ka0); ldsm_x4(bl0, ka0 + KV_KLO);
            ldsm_x4(bh1, ka1); ldsm_x4(bl1, ka1 + KV_KLO);
            mma16816(s[0], qh[c], bh0); mma16816(s[1], qh[c], bh0 + 2);
            mma16816(s[2], qh[c], bh1); mma16816(s[3], qh[c], bh1 + 2);
            mma16816(s[0], qh[c], bl0); mma16816(s[1], qh[c], bl0 + 2);
            mma16816(s[2], qh[c], bl1); mma16816(s[3], qh[c], bl1 + 2);
            mma16816(s[0], ql[c], bh0); mma16816(s[1], ql[c], bh0 + 2);
            mma16816(s[2], ql[c], bh1); mma16816(s[3], ql[c], bh1 + 2);
        }

        // ---- softmax in registers ----
        const unsigned w0 = mrow0[it];
        const unsigned w8 = mrow8[it];
#pragma unroll
        for (int j = 0; j < 4; j++) {
            const int bit = j * 8 + tig * 2;
            float p0 = __expf(s[j][0] * SC);
            float p1 = __expf(s[j][1] * SC);
            float p2 = __expf(s[j][2] * SC);
            float p3 = __expf(s[j][3] * SC);
            p0 = ((w0 >> bit) & 1u)       ? p0 : 0.f;
            p1 = ((w0 >> (bit + 1)) & 1u) ? p1 : 0.f;
            p2 = ((w8 >> bit) & 1u)       ? p2 : 0.f;
            p3 = ((w8 >> (bit + 1)) & 1u) ? p3 : 0.f;
            lsum_g += p0 + p1;
            lsum_8 += p2 + p3;
            s[j][0] = p0; s[j][1] = p1; s[j][2] = p2; s[j][3] = p3;
        }

        // ---- O += P V (2-term: P single fp16, V hi/lo) ----
#pragma unroll
        for (int c2 = 0; c2 < 2; c2++) {
            uint32_t ah[4];
            ah[0] = pack2h(s[2 * c2][0],     s[2 * c2][1]);
            ah[1] = pack2h(s[2 * c2][2],     s[2 * c2][3]);
            ah[2] = pack2h(s[2 * c2 + 1][0], s[2 * c2 + 1][1]);
            ah[3] = pack2h(s[2 * c2 + 1][2], s[2 * c2 + 1][3]);
#pragma unroll
            for (int jp = 0; jp < 4; jp++) {
                uint32_t bh[4], bl[4];
                const uint32_t va = kv + KV_VHI + voff +
                                    (uint32_t)(c2 * 16 * (PT * 2)) + jp * 32;
                ldsm_x4_t(bh, va);
                ldsm_x4_t(bl, va + (KV_VLO - KV_VHI));
                mma16816(o[2 * jp],     ah, bh);
                mma16816(o[2 * jp + 1], ah, bh + 2);
                mma16816(o[2 * jp],     ah, bl);
                mma16816(o[2 * jp + 1], ah, bl + 2);
            }
        }
    }

    // ---- epilogue: normalize, store single fp16 ----
    lsum_g += __shfl_xor_sync(0xffffffffu, lsum_g, 1);
    lsum_g += __shfl_xor_sync(0xffffffffu, lsum_g, 2);
    lsum_8 += __shfl_xor_sync(0xffffffffu, lsum_8, 1);
    lsum_8 += __shfl_xor_sync(0xffffffffu, lsum_8, 2);
    const float inv_g = 1.0f / lsum_g;
    const float inv_8 = 1.0f / lsum_8;

    const size_t d0 = (size_t)(n * S_LEN + qrow_g) * EMB + h * HD;
    const size_t d8 = d0 + (size_t)8 * EMB;
#pragma unroll
    for (int j = 0; j < 8; j++) {
        const int col = j * 8 + tig * 2;
        *(uint32_t*)(g_ao + d0 + col) = pack2h(o[j][0] * inv_g, o[j][1] * inv_g);
        *(uint32_t*)(g_ao + d8 + col) = pack2h(o[j][2] * inv_8, o[j][3] * inv_8);
    }
}

// ---------------------------------------------------------------------------
// Kernel 3: output projection — fp16 2-term (A single, Wo hi/lo), BK=32
// stage: A 0 / Bhi 10240 / Blo 20480 (pitch 80 B); 2 stages
// ---------------------------------------------------------------------------
#define OPKB    80
#define OB2_SZ  30720
#define OB2_BHI 10240
#define OB2_BLO 20480
#define OUT2_SMEM (2 * 30720 + 128)
#define ONIT2 (EMB / 32)

__global__ __launch_bounds__(256, 2)
void out_mma_kernel(const float* __restrict__ bo, float* __restrict__ out)
{
    extern __shared__ char sm[];
    const uint32_t smb = smem_u32(sm);

    const int tid = threadIdx.x, wid = tid >> 5, lane = tid & 31;
    const int r0 = blockIdx.y * 128;
    const int e0 = blockIdx.x * 128;
    const int wr = wid & 3;
    const int wc = wid >> 2;

    const int l7  = lane & 7;
    const int s01 = (lane >> 3) & 1;
    const int s23 = lane >> 4;
    const uint32_t aoff = (uint32_t)((l7 + s01 * 8) * OPKB) + s23 * 16;
    const uint32_t boff = (uint32_t)((s23 * 8 + l7) * OPKB) + s01 * 16;

    float acc[2][8][4];
#pragma unroll
    for (int m = 0; m < 2; m++)
#pragma unroll
        for (int j = 0; j < 8; j++)
#pragma unroll
            for (int u = 0; u < 4; u++) acc[m][j][u] = 0.f;

    const int ar0 = tid >> 2,          aq0 = tid & 3;
    const int ar1 = (tid + 256) >> 2,  aq1 = tid & 3;
    const uint32_t os0 = (uint32_t)(ar0 * OPKB + aq0 * 16);
    const uint32_t os1 = (uint32_t)(ar1 * OPKB + aq1 * 16);
    const size_t ag0 = (size_t)(r0 + ar0) * EMB + aq0 * 8;
    const size_t ag1 = (size_t)(r0 + ar1) * EMB + aq1 * 8;
    const size_t bg0 = (size_t)(e0 + ar0) * EMB + aq0 * 8;
    const size_t bg1 = (size_t)(e0 + ar1) * EMB + aq1 * 8;

    {
        const uint32_t d = smb;
        cp16(d + os0,           g_ao  + ag0);  cp16(d + os1,           g_ao  + ag1);
        cp16(d + OB2_BHI + os0, g_woh + bg0);  cp16(d + OB2_BHI + os1, g_woh + bg1);
        cp16(d + OB2_BLO + os0, g_wol + bg0);  cp16(d + OB2_BLO + os1, g_wol + bg1);
    }
    CP_COMMIT();

    for (int ic = 0; ic < ONIT2; ic++) {
        const uint32_t buf = smb + (ic & 1) * OB2_SZ;

        CP_WAIT0();
        __syncthreads();

        if (ic + 1 < ONIT2) {
            const int c1 = (ic + 1) * 32;
            const uint32_t d = smb + ((ic + 1) & 1) * OB2_SZ;
            cp16(d + os0,           g_ao  + ag0 + c1);  cp16(d + os1,           g_ao  + ag1 + c1);
            cp16(d + OB2_BHI + os0, g_woh + bg0 + c1);  cp16(d + OB2_BHI + os1, g_woh + bg1 + c1);
            cp16(d + OB2_BLO + os0, g_wol + bg0 + c1);  cp16(d + OB2_BLO + os1, g_wol + bg1 + c1);
        }
        CP_COMMIT();

#pragma unroll
        for (int kk = 0; kk < 2; kk++) {
            uint32_t ah0[4], ah1[4];
            const uint32_t aa0 = buf + (uint32_t)(wr * 32 * OPKB) + aoff + kk * 32;
            const uint32_t aa1 = aa0 + (uint32_t)(16 * OPKB);
            ldsm_x4(ah0, aa0);
            ldsm_x4(ah1, aa1);
#pragma unroll
            for (int jj = 0; jj < 4; jj++) {
                uint32_t bh[4], bl[4];
                const uint32_t ba = buf + OB2_BHI +
                    (uint32_t)((wc * 64 + jj * 16) * OPKB) + boff + kk * 32;
                ldsm_x4(bh, ba); ldsm_x4(bl, ba + (OB2_BLO - OB2_BHI));
                mma16816(acc[0][2 * jj],     ah0, bh); mma16816(acc[0][2 * jj + 1], ah0, bh + 2);
                mma16816(acc[1][2 * jj],     ah1, bh); mma16816(acc[1][2 * jj + 1], ah1, bh + 2);
                mma16816(acc[0][2 * jj],     ah0, bl); mma16816(acc[0][2 * jj + 1], ah0, bl + 2);
                mma16816(acc[1][2 * jj],     ah1, bl); mma16816(acc[1][2 * jj + 1], ah1, bl + 2);
            }
        }
    }

    const int g   = lane >> 2;
    const int tig = lane & 3;
#pragma unroll
    for (int m = 0; m < 2; m++) {
        const int row  = r0 + wr * 32 + m * 16 + g;
        const int row8 = row + 8;
#pragma unroll
        for (int jn = 0; jn < 8; jn++) {
            const int col = e0 + wc * 64 + jn * 8 + tig * 2;
            const float2 bb = *(const float2*)(bo + col);
            float2 v0 = make_float2(acc[m][jn][0] + bb.x, acc[m][jn][1] + bb.y);
            float2 v1 = make_float2(acc[m][jn][2] + bb.x, acc[m][jn][3] + bb.y);
            *(float2*)(out + (size_t)row  * EMB + col) = v0;
            *(float2*)(out + (size_t)row8 * EMB + col) = v1;
        }
    }
}

// ---------------------------------------------------------------------------
extern "C" void kernel_launch(void* const* d_in, const int* in_sizes, int n_in,
                              void* d_out, int out_size)
{
    const float* values  = (const float*)d_in[0];
    const float* queries = (const float*)d_in[1];
    const float* keys    = (const float*)d_in[2];
    const int*   mask    = (const int*)  d_in[3];
    const float* Wv      = (const float*)d_in[4];
    const float* Wk      = (const float*)d_in[5];
    const float* Wq      = (const float*)d_in[6];
    const float* Wo      = (const float*)d_in[7];
    const float* bo      = (const float*)d_in[8];
    float* out = (float*)d_out;

    static bool attr_set = false;
    if (!attr_set) {
        cudaFuncSetAttribute(proj_wmma_kernel,
                             cudaFuncAttributeMaxDynamicSharedMemorySize, PJ_SMEM);
        cudaFuncSetAttribute(attn_mma_kernel,
                             cudaFuncAttributeMaxDynamicSharedMemorySize, ATTN_SMEM);
        cudaFuncSetAttribute(out_mma_kernel,
                             cudaFuncAttributeMaxDynamicSharedMemorySize, OUT2_SMEM);
        attr_set = true;
    }

    mask_pack_kernel<<<(N_B * S_LEN * MWORDS * 32) / 256, 256>>>(mask);
    wo_split_kernel<<<(EMB * EMB) / (256 * 8), 256>>>(Wo);

    dim3 pgrid(S_LEN / 128, N_B * HEADS, 3);
    proj_wmma_kernel<<<pgrid, 256, PJ_SMEM>>>(queries, keys, values, Wq, Wk, Wv);

    dim3 agrid(HEADS, S_LEN / 128, N_B);
    attn_mma_kernel<<<agrid, 256, ATTN_SMEM>>>();

    dim3 ggrid(EMB / 128, (N_B * S_LEN) / 128);
    out_mma_kernel<<<ggrid, 256, OUT2_SMEM>>>(bo, out);
}

// round 12
// speedup vs baseline: 1.8814x; 1.4335x over previous
#include <cuda_runtime.h>
#include <cuda_fp16.h>
#include <mma.h>
#include <cstdint>

using namespace nvcuda;

#define N_B    4
#define S_LEN  2048
#define EMB    1024
#define HEADS  16
#define HD     64
#define MWORDS (S_LEN / 32)

#define PT   72    // fp16 smem pitch (144 B rows)
#define PSCR 20

// ---------------- scratch (device globals) ---------------------------------
__device__ __half g_q[N_B * HEADS * S_LEN * HD];    // single fp16
__device__ __half g_k[N_B * HEADS * S_LEN * HD];
__device__ __half g_v[N_B * HEADS * S_LEN * HD];
__device__ __half g_ao[N_B * S_LEN * EMB];
__device__ __half g_woh[EMB * EMB];
__device__ __half g_wol[EMB * EMB];
__device__ unsigned g_mbits[N_B * S_LEN * MWORDS];

__device__ __forceinline__ uint32_t pack2h(float a, float b) {
    __half2 h = __floats2half2_rn(a, b);
    return *reinterpret_cast<uint32_t*>(&h);
}
__device__ __forceinline__ void split2h(float x0, float x1, uint32_t& hi, uint32_t& lo) {
    __half h0 = __float2half_rn(x0), h1 = __float2half_rn(x1);
    float r0 = x0 - __half2float(h0), r1 = x1 - __half2float(h1);
    __half l0 = __float2half_rn(r0), l1 = __float2half_rn(r1);
    __half2 hp; hp.x = h0; hp.y = h1;
    __half2 lp; lp.x = l0; lp.y = l1;
    hi = *reinterpret_cast<uint32_t*>(&hp);
    lo = *reinterpret_cast<uint32_t*>(&lp);
}

__device__ __forceinline__ uint32_t smem_u32(const void* p) {
    uint32_t a;
    asm("{ .reg .u64 t; cvta.to.shared.u64 t, %1; cvt.u32.u64 %0, t; }"
        : "=r"(a) : "l"(p));
    return a;
}

// ---- tensor-core / async-copy primitives ----------------------------------
__device__ __forceinline__ void ldsm_x4(uint32_t* r, uint32_t addr) {
    asm volatile("ldmatrix.sync.aligned.m8n8.x4.shared.b16 {%0,%1,%2,%3}, [%4];"
                 : "=r"(r[0]), "=r"(r[1]), "=r"(r[2]), "=r"(r[3]) : "r"(addr));
}
__device__ __forceinline__ void ldsm_x4_t(uint32_t* r, uint32_t addr) {
    asm volatile("ldmatrix.sync.aligned.m8n8.x4.trans.shared.b16 {%0,%1,%2,%3}, [%4];"
                 : "=r"(r[0]), "=r"(r[1]), "=r"(r[2]), "=r"(r[3]) : "r"(addr));
}
__device__ __forceinline__ void mma16816(float* d, const uint32_t* a, const uint32_t* b) {
    asm volatile(
        "mma.sync.aligned.m16n8k16.row.col.f32.f16.f16.f32 "
        "{%0,%1,%2,%3}, {%4,%5,%6,%7}, {%8,%9}, {%0,%1,%2,%3};"
        : "+f"(d[0]), "+f"(d[1]), "+f"(d[2]), "+f"(d[3])
        : "r"(a[0]), "r"(a[1]), "r"(a[2]), "r"(a[3]), "r"(b[0]), "r"(b[1]));
}
__device__ __forceinline__ void cp16(uint32_t dst, const void* src) {
    asm volatile("cp.async.cg.shared.global [%0], [%1], 16;" :: "r"(dst), "l"(src));
}
#define CP_COMMIT() asm volatile("cp.async.commit_group;" ::: "memory")
#define CP_WAIT0()  asm volatile("cp.async.wait_group 0;" ::: "memory")

// stage nrows x 64 f32 -> fp16 hi/lo smem pitch PT (proj inputs)
__device__ __forceinline__ void stage_rows_f32(const float* __restrict__ src, size_t stride,
                                               char* s_hi, char* s_lo, int t)
{
    const int r    = t >> 1;
    const int half = t & 1;
    const float4* s4 = (const float4*)(src + (size_t)r * stride) + half * 8;
#pragma unroll
    for (int tt = 0; tt < 4; tt++) {
        float4 a = s4[2 * tt], b = s4[2 * tt + 1];
        float f[8] = {a.x, a.y, a.z, a.w, b.x, b.y, b.z, b.w};
        uint32_t H[4], L[4];
#pragma unroll
        for (int u = 0; u < 4; u++) split2h(f[2 * u], f[2 * u + 1], H[u], L[u]);
        uint32_t off = (uint32_t)(r * (PT * 2) + half * 64 + tt * 16);
        *(uint4*)(s_hi + off) = make_uint4(H[0], H[1], H[2], H[3]);
        *(uint4*)(s_lo + off) = make_uint4(L[0], L[1], L[2], L[3]);
    }
}

// ---------------------------------------------------------------------------
// Kernel 0a: pack mask bits
// ---------------------------------------------------------------------------
__global__ __launch_bounds__(256)
void mask_pack_kernel(const int* __restrict__ mask)
{
    int gid  = blockIdx.x * 256 + threadIdx.x;
    int w    = gid >> 5;
    int lane = gid & 31;
    int v = mask[(size_t)w * 32 + lane];
    unsigned bits = __ballot_sync(0xffffffffu, v != 0);
    if (lane == 0) g_mbits[w] = bits;
}

// ---------------------------------------------------------------------------
// Kernel 0b: pre-split Wo into fp16 hi/lo
// ---------------------------------------------------------------------------
__global__ __launch_bounds__(256)
void wo_split_kernel(const float* __restrict__ Wo)
{
    size_t idx = ((size_t)blockIdx.x * 256 + threadIdx.x) * 8;
    float4 a = *(const float4*)(Wo + idx);
    float4 b = *(const float4*)(Wo + idx + 4);
    float f[8] = {a.x, a.y, a.z, a.w, b.x, b.y, b.z, b.w};
    uint32_t H[4], L[4];
#pragma unroll
    for (int u = 0; u < 4; u++) split2h(f[2 * u], f[2 * u + 1], H[u], L[u]);
    *(uint4*)(g_woh + idx) = make_uint4(H[0], H[1], H[2], H[3]);
    *(uint4*)(g_wol + idx) = make_uint4(L[0], L[1], L[2], L[3]);
}

// ---------------------------------------------------------------------------
// Kernel 1: projections via wmma fp16 3-term; outputs SINGLE fp16 Q/K/V
// ---------------------------------------------------------------------------
#define PJ_WHI 0
#define PJ_WLO 9216
#define PJ_XHI 18432
#define PJ_XLO 36864
#define PJ_SCR 55296
#define PJ_SMEM (55296 + 10240)

__global__ __launch_bounds__(256, 2)
void proj_wmma_kernel(const float* __restrict__ xq, const float* __restrict__ xk,
                      const float* __restrict__ xv,
                      const float* __restrict__ Wq, const float* __restrict__ Wk,
                      const float* __restrict__ Wv)
{
    extern __shared__ char sm[];
    __half* Whi = (__half*)(sm + PJ_WHI);
    __half* Wlo = (__half*)(sm + PJ_WLO);
    __half* Xhi = (__half*)(sm + PJ_XHI);
    __half* Xlo = (__half*)(sm + PJ_XLO);

    const int which = blockIdx.z;
    const float* X; const float* W; __half* Y;
    if (which == 0)      { X = xq; W = Wq; Y = g_q; }
    else if (which == 1) { X = xk; W = Wk; Y = g_k; }
    else                 { X = xv; W = Wv; Y = g_v; }

    const int nh = blockIdx.y;
    const int n  = nh / HEADS;
    const int h  = nh % HEADS;
    const int s0 = blockIdx.x * 128;
    const int tid = threadIdx.x, wid = tid >> 5, lane = tid & 31;
    float* scr = (float*)(sm + PJ_SCR) + wid * (16 * PSCR);

    stage_rows_f32(X + (size_t)(n * S_LEN + s0) * EMB + h * HD, EMB,
                   (char*)Xhi, (char*)Xlo, tid);
    if (tid < 128)
        stage_rows_f32(W, HD, (char*)Whi, (char*)Wlo, tid);
    __syncthreads();

    wmma::fragment<wmma::accumulator, 16, 16, 16, float> acc[4];
#pragma unroll
    for (int j = 0; j < 4; j++) wmma::fill_fragment(acc[j], 0.0f);

#pragma unroll
    for (int kk = 0; kk < 4; kk++) {
        wmma::fragment<wmma::matrix_a, 16, 16, 16, __half, wmma::row_major> ah, al;
        wmma::load_matrix_sync(ah, Xhi + wid * 16 * PT + kk * 16, PT);
        wmma::load_matrix_sync(al, Xlo + wid * 16 * PT + kk * 16, PT);
#pragma unroll
        for (int j = 0; j < 4; j++) {
            wmma::fragment<wmma::matrix_b, 16, 16, 16, __half, wmma::col_major> bh, bl;
            wmma::load_matrix_sync(bh, Whi + j * 16 * PT + kk * 16, PT);
            wmma::load_matrix_sync(bl, Wlo + j * 16 * PT + kk * 16, PT);
            wmma::mma_sync(acc[j], ah, bh, acc[j]);
            wmma::mma_sync(acc[j], ah, bl, acc[j]);
            wmma::mma_sync(acc[j], al, bh, acc[j]);
        }
    }

    const int r = lane >> 1, cw = lane & 1;
    const size_t ybase = (size_t)((n * HEADS + h) * S_LEN + s0 + wid * 16) * HD;
#pragma unroll
    for (int j = 0; j < 4; j++) {
        wmma::store_matrix_sync(scr, acc[j], PSCR, wmma::mem_row_major);
        __syncwarp();
        const float* s = scr + r * PSCR + cw * 8;
        uint32_t H[4];
#pragma unroll
        for (int u = 0; u < 4; u++) H[u] = pack2h(s[2 * u], s[2 * u + 1]);
        *(uint4*)(Y + ybase + (size_t)r * HD + j * 16 + cw * 8) =
            make_uint4(H[0], H[1], H[2], H[3]);
        __syncwarp();
    }
}

// ---------------------------------------------------------------------------
// Kernel 2: flash attention — SINGLE fp16 QK and V; fp32 accum
// grid (HEADS, S_LEN/128, N_B), 256 threads, kv-tile 32, 2-stage cp.async
// smem: Q 18432 + 2 KV stages of 9216 (K 0 / V 4608)
// ---------------------------------------------------------------------------
#define A_Q    0
#define A_KV0  18432
#define A_KV1  27648
#define KV_V   4608
#define ATTN_SMEM (36864 + 256)
#define NIT (S_LEN / 32)

__global__ __launch_bounds__(256, 2)
void attn_mma_kernel()
{
    extern __shared__ char sm[];
    const int tid = threadIdx.x, wid = tid >> 5, lane = tid & 31;
    const int h = blockIdx.x, qt = blockIdx.y, n = blockIdx.z;
    const int q0 = qt * 128;

    const size_t head_base = (size_t)(n * HEADS + h) * S_LEN * HD;
    const __half* Q = g_q + head_base + (size_t)q0 * HD;
    const __half* K = g_k + head_base;
    const __half* V = g_v + head_base;

    const uint32_t smb = smem_u32(sm);

    // ---- prefetch KV tile 0 ----
    const int str = tid >> 3, soct = tid & 7;
    const uint32_t soff = (uint32_t)(str * (PT * 2) + soct * 16);
    {
        const size_t gsrc = (size_t)str * HD + soct * 8;
        cp16(smb + A_KV0 + soff,        K + gsrc);
        cp16(smb + A_KV0 + KV_V + soff, V + gsrc);
    }
    CP_COMMIT();

    // ---- stage Q (single fp16), hoist fragments ----
    {
        const int r = tid >> 1, half = tid & 1;
        const char* sq = (const char*)(Q + (size_t)r * HD + half * 32);
        uint32_t off = (uint32_t)(r * (PT * 2) + half * 64);
#pragma unroll
        for (int tt = 0; tt < 4; tt++)
            *(uint4*)(sm + A_Q + off + tt * 16) = *(const uint4*)(sq + tt * 16);
    }
    __syncthreads();

    const int l7  = lane & 7;
    const int s01 = (lane >> 3) & 1;
    const int s23 = (lane >> 4) & 1;

    uint32_t qh[4][4];
    {
        uint32_t base = smb + (uint32_t)((wid * 16 + l7 + s01 * 8) * (PT * 2)) + s23 * 16;
#pragma unroll
        for (int c = 0; c < 4; c++)
            ldsm_x4(qh[c], base + A_Q + c * 32);
    }

    const int g   = lane >> 2;
    const int tig = lane & 3;
    const int qrow_g  = q0 + wid * 16 + g;
    const unsigned* mrow0 = g_mbits + (size_t)(n * S_LEN + qrow_g) * MWORDS;
    const unsigned* mrow8 = mrow0 + 8 * MWORDS;

    const uint32_t kqoff = (uint32_t)(((lane >> 4) * 8 + l7) * (PT * 2)) + ((lane >> 3) & 1) * 16;
    const uint32_t voff  = (uint32_t)((((lane >> 3) & 1) * 8 + l7) * (PT * 2)) + (lane >> 4) * 16;

    float o[8][4];
#pragma unroll
    for (int j = 0; j < 8; j++)
#pragma unroll
        for (int u = 0; u < 4; u++) o[j][u] = 0.f;
    float lsum_g = 0.f, lsum_8 = 0.f;

    const float SC = 0.03125f;

    for (int it = 0; it < NIT; it++) {
        const uint32_t kv = smb + ((it & 1) ? A_KV1 : A_KV0);

        CP_WAIT0();
        __syncthreads();

        if (it + 1 < NIT) {
            const size_t gsrc = (size_t)((it + 1) * 32 + str) * HD + soct * 8;
            const uint32_t d = smb + (((it + 1) & 1) ? A_KV1 : A_KV0);
            cp16(d + soff,        K + gsrc);
            cp16(d + KV_V + soff, V + gsrc);
        }
        CP_COMMIT();

        // ---- S = Q K^T (single fp16: 4 MMAs per k-chunk) ----
        float s[4][4];
#pragma unroll
        for (int j = 0; j < 4; j++)
#pragma unroll
            for (int u = 0; u < 4; u++) s[j][u] = 0.f;

#pragma unroll
        for (int c = 0; c < 4; c++) {
            uint32_t bh0[4], bh1[4];
            const uint32_t ka0 = kv + kqoff + c * 32;
            const uint32_t ka1 = ka0 + (uint32_t)(16 * (PT * 2));
            ldsm_x4(bh0, ka0);
            ldsm_x4(bh1, ka1);
            mma16816(s[0], qh[c], bh0); mma16816(s[1], qh[c], bh0 + 2);
            mma16816(s[2], qh[c], bh1); mma16816(s[3], qh[c], bh1 + 2);
        }

        // ---- softmax in registers ----
        const unsigned w0 = mrow0[it];
        const unsigned w8 = mrow8[it];
#pragma unroll
        for (int j = 0; j < 4; j++) {
            const int bit = j * 8 + tig * 2;
            float p0 = __expf(s[j][0] * SC);
            float p1 = __expf(s[j][1] * SC);
            float p2 = __expf(s[j][2] * SC);
            float p3 = __expf(s[j][3] * SC);
            p0 = ((w0 >> bit) & 1u)       ? p0 : 0.f;
            p1 = ((w0 >> (bit + 1)) & 1u) ? p1 : 0.f;
            p2 = ((w8 >> bit) & 1u)       ? p2 : 0.f;
            p3 = ((w8 >> (bit + 1)) & 1u) ? p3 : 0.f;
            lsum_g += p0 + p1;
            lsum_8 += p2 + p3;
            s[j][0] = p0; s[j][1] = p1; s[j][2] = p2; s[j][3] = p3;
        }

        // ---- O += P V (single fp16 P and V) ----
#pragma unroll
        for (int c2 = 0; c2 < 2; c2++) {
            uint32_t ah[4];
            ah[0] = pack2h(s[2 * c2][0],     s[2 * c2][1]);
            ah[1] = pack2h(s[2 * c2][2],     s[2 * c2][3]);
            ah[2] = pack2h(s[2 * c2 + 1][0], s[2 * c2 + 1][1]);
            ah[3] = pack2h(s[2 * c2 + 1][2], s[2 * c2 + 1][3]);
#pragma unroll
            for (int jp = 0; jp < 4; jp++) {
                uint32_t bh[4];
                const uint32_t va = kv + KV_V + voff +
                                    (uint32_t)(c2 * 16 * (PT * 2)) + jp * 32;
                ldsm_x4_t(bh, va);
                mma16816(o[2 * jp],     ah, bh);
                mma16816(o[2 * jp + 1], ah, bh + 2);
            }
        }
    }

    // ---- epilogue: normalize, store single fp16 ----
    lsum_g += __shfl_xor_sync(0xffffffffu, lsum_g, 1);
    lsum_g += __shfl_xor_sync(0xffffffffu, lsum_g, 2);
    lsum_8 += __shfl_xor_sync(0xffffffffu, lsum_8, 1);
    lsum_8 += __shfl_xor_sync(0xffffffffu, lsum_8, 2);
    const float inv_g = 1.0f / lsum_g;
    const float inv_8 = 1.0f / lsum_8;

    const size_t d0 = (size_t)(n * S_LEN + qrow_g) * EMB + h * HD;
    const size_t d8 = d0 + (size_t)8 * EMB;
#pragma unroll
    for (int j = 0; j < 8; j++) {
        const int col = j * 8 + tig * 2;
        *(uint32_t*)(g_ao + d0 + col) = pack2h(o[j][0] * inv_g, o[j][1] * inv_g);
        *(uint32_t*)(g_ao + d8 + col) = pack2h(o[j][2] * inv_8, o[j][3] * inv_8);
    }
}

// ---------------------------------------------------------------------------
// Kernel 3: output projection — fp16 2-term (A single, Wo hi/lo), BK=32
// (unchanged from R11)
// ---------------------------------------------------------------------------
#define OPKB    80
#define OB2_SZ  30720
#define OB2_BHI 10240
#define OB2_BLO 20480
#define OUT2_SMEM (2 * 30720 + 128)
#define ONIT2 (EMB / 32)

__global__ __launch_bounds__(256, 2)
void out_mma_kernel(const float* __restrict__ bo, float* __restrict__ out)
{
    extern __shared__ char sm[];
    const uint32_t smb = smem_u32(sm);

    const int tid = threadIdx.x, wid = tid >> 5, lane = tid & 31;
    const int r0 = blockIdx.y * 128;
    const int e0 = blockIdx.x * 128;
    const int wr = wid & 3;
    const int wc = wid >> 2;

    const int l7  = lane & 7;
    const int s01 = (lane >> 3) & 1;
    const int s23 = lane >> 4;
    const uint32_t aoff = (uint32_t)((l7 + s01 * 8) * OPKB) + s23 * 16;
    const uint32_t boff = (uint32_t)((s23 * 8 + l7) * OPKB) + s01 * 16;

    float acc[2][8][4];
#pragma unroll
    for (int m = 0; m < 2; m++)
#pragma unroll
        for (int j = 0; j < 8; j++)
#pragma unroll
            for (int u = 0; u < 4; u++) acc[m][j][u] = 0.f;

    const int ar0 = tid >> 2,          aq0 = tid & 3;
    const int ar1 = (tid + 256) >> 2,  aq1 = tid & 3;
    const uint32_t os0 = (uint32_t)(ar0 * OPKB + aq0 * 16);
    const uint32_t os1 = (uint32_t)(ar1 * OPKB + aq1 * 16);
    const size_t ag0 = (size_t)(r0 + ar0) * EMB + aq0 * 8;
    const size_t ag1 = (size_t)(r0 + ar1) * EMB + aq1 * 8;
    const size_t bg0 = (size_t)(e0 + ar0) * EMB + aq0 * 8;
    const size_t bg1 = (size_t)(e0 + ar1) * EMB + aq1 * 8;

    {
        const uint32_t d = smb;
        cp16(d + os0,           g_ao  + ag0);  cp16(d + os1,           g_ao  + ag1);
        cp16(d + OB2_BHI + os0, g_woh + bg0);  cp16(d + OB2_BHI + os1, g_woh + bg1);
        cp16(d + OB2_BLO + os0, g_wol + bg0);  cp16(d + OB2_BLO + os1, g_wol + bg1);
    }
    CP_COMMIT();

    for (int ic = 0; ic < ONIT2; ic++) {
        const uint32_t buf = smb + (ic & 1) * OB2_SZ;

        CP_WAIT0();
        __syncthreads();

        if (ic + 1 < ONIT2) {
            const int c1 = (ic + 1) * 32;
            const uint32_t d = smb + ((ic + 1) & 1) * OB2_SZ;
            cp16(d + os0,           g_ao  + ag0 + c1);  cp16(d + os1,           g_ao  + ag1 + c1);
            cp16(d + OB2_BHI + os0, g_woh + bg0 + c1);  cp16(d + OB2_BHI + os1, g_woh + bg1 + c1);
            cp16(d + OB2_BLO + os0, g_wol + bg0 + c1);  cp16(d + OB2_BLO + os1, g_wol + bg1 + c1);
        }
        CP_COMMIT();

#pragma unroll
        for (int kk = 0; kk < 2; kk++) {
            uint32_t ah0[4], ah1[4];
            const uint32_t aa0 = buf + (uint32_t)(wr * 32 * OPKB) + aoff + kk * 32;
            const uint32_t aa1 = aa0 + (uint32_t)(16 * OPKB);
            ldsm_x4(ah0, aa0);
            ldsm_x4(ah1, aa1);
#pragma unroll
            for (int jj = 0; jj < 4; jj++) {
                uint32_t bh[4], bl[4];
                const uint32_t ba = buf + OB2_BHI +
                    (uint32_t)((wc * 64 + jj * 16) * OPKB) + boff + kk * 32;
                ldsm_x4(bh, ba); ldsm_x4(bl, ba + (OB2_BLO - OB2_BHI));
                mma16816(acc[0][2 * jj],     ah0, bh); mma16816(acc[0][2 * jj + 1], ah0, bh + 2);
                mma16816(acc[1][2 * jj],     ah1, bh); mma16816(acc[1][2 * jj + 1], ah1, bh + 2);
                mma16816(acc[0][2 * jj],     ah0, bl); mma16816(acc[0][2 * jj + 1], ah0, bl + 2);
                mma16816(acc[1][2 * jj],     ah1, bl); mma16816(acc[1][2 * jj + 1], ah1, bl + 2);
            }
        }
    }

    const int g   = lane >> 2;
    const int tig = lane & 3;
#pragma unroll
    for (int m = 0; m < 2; m++) {
        const int row  = r0 + wr * 32 + m * 16 + g;
        const int row8 = row + 8;
#pragma unroll
        for (int jn = 0; jn < 8; jn++) {
            const int col = e0 + wc * 64 + jn * 8 + tig * 2;
            const float2 bb = *(const float2*)(bo + col);
            float2 v0 = make_float2(acc[m][jn][0] + bb.x, acc[m][jn][1] + bb.y);
            float2 v1 = make_float2(acc[m][jn][2] + bb.x, acc[m][jn][3] + bb.y);
            *(float2*)(out + (size_t)row  * EMB + col) = v0;
            *(float2*)(out + (size_t)row8 * EMB + col) = v1;
        }
    }
}

// ---------------------------------------------------------------------------
extern "C" void kernel_launch(void* const* d_in, const int* in_sizes, int n_in,
                              void* d_out, int out_size)
{
    const float* values  = (const float*)d_in[0];
    const float* queries = (const float*)d_in[1];
    const float* keys    = (const float*)d_in[2];
    const int*   mask    = (const int*)  d_in[3];
    const float* Wv      = (const float*)d_in[4];
    const float* Wk      = (const float*)d_in[5];
    const float* Wq      = (const float*)d_in[6];
    const float* Wo      = (const float*)d_in[7];
    const float* bo      = (const float*)d_in[8];
    float* out = (float*)d_out;

    static bool attr_set = false;
    if (!attr_set) {
        cudaFuncSetAttribute(proj_wmma_kernel,
                             cudaFuncAttributeMaxDynamicSharedMemorySize, PJ_SMEM);
        cudaFuncSetAttribute(attn_mma_kernel,
                             cudaFuncAttributeMaxDynamicSharedMemorySize, ATTN_SMEM);
        cudaFuncSetAttribute(out_mma_kernel,
                             cudaFuncAttributeMaxDynamicSharedMemorySize, OUT2_SMEM);
        attr_set = true;
    }

    mask_pack_kernel<<<(N_B * S_LEN * MWORDS * 32) / 256, 256>>>(mask);
    wo_split_kernel<<<(EMB * EMB) / (256 * 8), 256>>>(Wo);

    dim3 pgrid(S_LEN / 128, N_B * HEADS, 3);
    proj_wmma_kernel<<<pgrid, 256, PJ_SMEM>>>(queries, keys, values, Wq, Wk, Wv);

    dim3 agrid(HEADS, S_LEN / 128, N_B);
    attn_mma_kernel<<<agrid, 256, ATTN_SMEM>>>();

    dim3 ggrid(EMB / 128, (N_B * S_LEN) / 128);
    out_mma_kernel<<<ggrid, 256, OUT2_SMEM>>>(bo, out);
}

// round 13
// speedup vs baseline: 2.1272x; 1.1307x over previous
#include <cuda_runtime.h>
#include <cuda_fp16.h>
#include <mma.h>
#include <cstdint>

using namespace nvcuda;

#define N_B    4
#define S_LEN  2048
#define EMB    1024
#define HEADS  16
#define HD     64
#define MWORDS (S_LEN / 32)

#define PT   72    // fp16 smem pitch (144 B rows)
#define PSCR 20

// ---------------- scratch (device globals) ---------------------------------
__device__ __half g_q[N_B * HEADS * S_LEN * HD];    // single fp16, pre-scaled 1/32
__device__ __half g_k[N_B * HEADS * S_LEN * HD];
__device__ __half g_v[N_B * HEADS * S_LEN * HD];
__device__ __half g_ao[N_B * S_LEN * EMB];
__device__ __half g_wo[EMB * EMB];                  // single fp16
__device__ unsigned g_mbits[N_B * S_LEN * MWORDS];

__device__ __forceinline__ uint32_t pack2h(float a, float b) {
    __half2 h = __floats2half2_rn(a, b);
    return *reinterpret_cast<uint32_t*>(&h);
}
__device__ __forceinline__ void split2h(float x0, float x1, uint32_t& hi, uint32_t& lo) {
    __half h0 = __float2half_rn(x0), h1 = __float2half_rn(x1);
    float r0 = x0 - __half2float(h0), r1 = x1 - __half2float(h1);
    __half l0 = __float2half_rn(r0), l1 = __float2half_rn(r1);
    __half2 hp; hp.x = h0; hp.y = h1;
    __half2 lp; lp.x = l0; lp.y = l1;
    hi = *reinterpret_cast<uint32_t*>(&hp);
    lo = *reinterpret_cast<uint32_t*>(&lp);
}

__device__ __forceinline__ uint32_t smem_u32(const void* p) {
    uint32_t a;
    asm("{ .reg .u64 t; cvta.to.shared.u64 t, %1; cvt.u32.u64 %0, t; }"
        : "=r"(a) : "l"(p));
    return a;
}

// ---- tensor-core / async-copy primitives ----------------------------------
__device__ __forceinline__ void ldsm_x4(uint32_t* r, uint32_t addr) {
    asm volatile("ldmatrix.sync.aligned.m8n8.x4.shared.b16 {%0,%1,%2,%3}, [%4];"
                 : "=r"(r[0]), "=r"(r[1]), "=r"(r[2]), "=r"(r[3]) : "r"(addr));
}
__device__ __forceinline__ void ldsm_x4_t(uint32_t* r, uint32_t addr) {
    asm volatile("ldmatrix.sync.aligned.m8n8.x4.trans.shared.b16 {%0,%1,%2,%3}, [%4];"
                 : "=r"(r[0]), "=r"(r[1]), "=r"(r[2]), "=r"(r[3]) : "r"(addr));
}
__device__ __forceinline__ void mma16816(float* d, const uint32_t* a, const uint32_t* b) {
    asm volatile(
        "mma.sync.aligned.m16n8k16.row.col.f32.f16.f16.f32 "
        "{%0,%1,%2,%3}, {%4,%5,%6,%7}, {%8,%9}, {%0,%1,%2,%3};"
        : "+f"(d[0]), "+f"(d[1]), "+f"(d[2]), "+f"(d[3])
        : "r"(a[0]), "r"(a[1]), "r"(a[2]), "r"(a[3]), "r"(b[0]), "r"(b[1]));
}
__device__ __forceinline__ void cp16(uint32_t dst, const void* src) {
    asm volatile("cp.async.cg.shared.global [%0], [%1], 16;" :: "r"(dst), "l"(src));
}
#define CP_COMMIT() asm volatile("cp.async.commit_group;" ::: "memory")
#define CP_WAIT0()  asm volatile("cp.async.wait_group 0;" ::: "memory")

// stage nrows x 64 f32 -> fp16 hi/lo smem pitch PT (W in proj)
__device__ __forceinline__ void stage_rows_f32(const float* __restrict__ src, size_t stride,
                                               char* s_hi, char* s_lo, int t)
{
    const int r    = t >> 1;
    const int half = t & 1;
    const float4* s4 = (const float4*)(src + (size_t)r * stride) + half * 8;
#pragma unroll
    for (int tt = 0; tt < 4; tt++) {
        float4 a = s4[2 * tt], b = s4[2 * tt + 1];
        float f[8] = {a.x, a.y, a.z, a.w, b.x, b.y, b.z, b.w};
        uint32_t H[4], L[4];
#pragma unroll
        for (int u = 0; u < 4; u++) split2h(f[2 * u], f[2 * u + 1], H[u], L[u]);
        uint32_t off = (uint32_t)(r * (PT * 2) + half * 64 + tt * 16);
        *(uint4*)(s_hi + off) = make_uint4(H[0], H[1], H[2], H[3]);
        *(uint4*)(s_lo + off) = make_uint4(L[0], L[1], L[2], L[3]);
    }
}

// stage nrows x 64 f32 -> SINGLE fp16 smem pitch PT (X in proj)
__device__ __forceinline__ void stage_rows_f32_single(const float* __restrict__ src,
                                                      size_t stride, char* s_x, int t)
{
    const int r    = t >> 1;
    const int half = t & 1;
    const float4* s4 = (const float4*)(src + (size_t)r * stride) + half * 8;
#pragma unroll
    for (int tt = 0; tt < 4; tt++) {
        float4 a = s4[2 * tt], b = s4[2 * tt + 1];
        uint32_t H[4];
        H[0] = pack2h(a.x, a.y); H[1] = pack2h(a.z, a.w);
        H[2] = pack2h(b.x, b.y); H[3] = pack2h(b.z, b.w);
        uint32_t off = (uint32_t)(r * (PT * 2) + half * 64 + tt * 16);
        *(uint4*)(s_x + off) = make_uint4(H[0], H[1], H[2], H[3]);
    }
}

// ---------------------------------------------------------------------------
// Kernel 0a: pack mask bits
// ---------------------------------------------------------------------------
__global__ __launch_bounds__(256)
void mask_pack_kernel(const int* __restrict__ mask)
{
    int gid  = blockIdx.x * 256 + threadIdx.x;
    int w    = gid >> 5;
    int lane = gid & 31;
    int v = mask[(size_t)w * 32 + lane];
    unsigned bits = __ballot_sync(0xffffffffu, v != 0);
    if (lane == 0) g_mbits[w] = bits;
}

// ---------------------------------------------------------------------------
// Kernel 0b: convert Wo to single fp16
// ---------------------------------------------------------------------------
__global__ __launch_bounds__(256)
void wo_half_kernel(const float* __restrict__ Wo)
{
    size_t idx = ((size_t)blockIdx.x * 256 + threadIdx.x) * 8;
    float4 a = *(const float4*)(Wo + idx);
    float4 b = *(const float4*)(Wo + idx + 4);
    uint32_t H[4];
    H[0] = pack2h(a.x, a.y); H[1] = pack2h(a.z, a.w);
    H[2] = pack2h(b.x, b.y); H[3] = pack2h(b.z, b.w);
    *(uint4*)(g_wo + idx) = make_uint4(H[0], H[1], H[2], H[3]);
}

// ---------------------------------------------------------------------------
// Kernel 1: projections — X single fp16, W hi/lo (2-term); Q pre-scaled 1/32
// ---------------------------------------------------------------------------
#define PJ_WHI 0
#define PJ_WLO 9216
#define PJ_X   18432
#define PJ_SCR 36864
#define PJ_SMEM (36864 + 10240)

__global__ __launch_bounds__(256, 2)
void proj_wmma_kernel(const float* __restrict__ xq, const float* __restrict__ xk,
                      const float* __restrict__ xv,
                      const float* __restrict__ Wq, const float* __restrict__ Wk,
                      const float* __restrict__ Wv)
{
    extern __shared__ char sm[];
    __half* Whi = (__half*)(sm + PJ_WHI);
    __half* Wlo = (__half*)(sm + PJ_WLO);
    __half* Xs  = (__half*)(sm + PJ_X);

    const int which = blockIdx.z;
    const float* X; const float* W; __half* Y;
    if (which == 0)      { X = xq; W = Wq; Y = g_q; }
    else if (which == 1) { X = xk; W = Wk; Y = g_k; }
    else                 { X = xv; W = Wv; Y = g_v; }
    const float oscale = (which == 0) ? 0.03125f : 1.0f;   // fold 1/sqrt(EMB) into Q

    const int nh = blockIdx.y;
    const int n  = nh / HEADS;
    const int h  = nh % HEADS;
    const int s0 = blockIdx.x * 128;
    const int tid = threadIdx.x, wid = tid >> 5, lane = tid & 31;
    float* scr = (float*)(sm + PJ_SCR) + wid * (16 * PSCR);

    stage_rows_f32_single(X + (size_t)(n * S_LEN + s0) * EMB + h * HD, EMB,
                          (char*)Xs, tid);
    if (tid < 128)
        stage_rows_f32(W, HD, (char*)Whi, (char*)Wlo, tid);
    __syncthreads();

    wmma::fragment<wmma::accumulator, 16, 16, 16, float> acc[4];
#pragma unroll
    for (int j = 0; j < 4; j++) wmma::fill_fragment(acc[j], 0.0f);

#pragma unroll
    for (int kk = 0; kk < 4; kk++) {
        wmma::fragment<wmma::matrix_a, 16, 16, 16, __half, wmma::row_major> ax;
        wmma::load_matrix_sync(ax, Xs + wid * 16 * PT + kk * 16, PT);
#pragma unroll
        for (int j = 0; j < 4; j++) {
            wmma::fragment<wmma::matrix_b, 16, 16, 16, __half, wmma::col_major> bh, bl;
            wmma::load_matrix_sync(bh, Whi + j * 16 * PT + kk * 16, PT);
            wmma::load_matrix_sync(bl, Wlo + j * 16 * PT + kk * 16, PT);
            wmma::mma_sync(acc[j], ax, bh, acc[j]);
            wmma::mma_sync(acc[j], ax, bl, acc[j]);
        }
    }

    const int r = lane >> 1, cw = lane & 1;
    const size_t ybase = (size_t)((n * HEADS + h) * S_LEN + s0 + wid * 16) * HD;
#pragma unroll
    for (int j = 0; j < 4; j++) {
        wmma::store_matrix_sync(scr, acc[j], PSCR, wmma::mem_row_major);
        __syncwarp();
        const float* s = scr + r * PSCR + cw * 8;
        uint32_t H[4];
#pragma unroll
        for (int u = 0; u < 4; u++)
            H[u] = pack2h(s[2 * u] * oscale, s[2 * u + 1] * oscale);
        *(uint4*)(Y + ybase + (size_t)r * HD + j * 16 + cw * 8) =
            make_uint4(H[0], H[1], H[2], H[3]);
        __syncwarp();
    }
}

// ---------------------------------------------------------------------------
// Kernel 2: flash attention — single fp16 everywhere, Q pre-scaled
// grid (HEADS, S_LEN/128, N_B), 256 threads, kv-tile 32, 2-stage cp.async
// ---------------------------------------------------------------------------
#define A_Q    0
#define A_KV0  18432
#define A_KV1  27648
#define KV_V   4608
#define ATTN_SMEM (36864 + 256)
#define NIT (S_LEN / 32)

__global__ __launch_bounds__(256, 2)
void attn_mma_kernel()
{
    extern __shared__ char sm[];
    const int tid = threadIdx.x, wid = tid >> 5, lane = tid & 31;
    const int h = blockIdx.x, qt = blockIdx.y, n = blockIdx.z;
    const int q0 = qt * 128;

    const size_t head_base = (size_t)(n * HEADS + h) * S_LEN * HD;
    const __half* Q = g_q + head_base + (size_t)q0 * HD;
    const __half* K = g_k + head_base;
    const __half* V = g_v + head_base;

    const uint32_t smb = smem_u32(sm);

    // ---- prefetch KV tile 0 ----
    const int str = tid >> 3, soct = tid & 7;
    const uint32_t soff = (uint32_t)(str * (PT * 2) + soct * 16);
    {
        const size_t gsrc = (size_t)str * HD + soct * 8;
        cp16(smb + A_KV0 + soff,        K + gsrc);
        cp16(smb + A_KV0 + KV_V + soff, V + gsrc);
    }
    CP_COMMIT();

    // ---- stage Q (single fp16), hoist fragments ----
    {
        const int r = tid >> 1, half = tid & 1;
        const char* sq = (const char*)(Q + (size_t)r * HD + half * 32);
        uint32_t off = (uint32_t)(r * (PT * 2) + half * 64);
#pragma unroll
        for (int tt = 0; tt < 4; tt++)
            *(uint4*)(sm + A_Q + off + tt * 16) = *(const uint4*)(sq + tt * 16);
    }
    __syncthreads();

    const int l7  = lane & 7;
    const int s01 = (lane >> 3) & 1;
    const int s23 = (lane >> 4) & 1;

    uint32_t qh[4][4];
    {
        uint32_t base = smb + (uint32_t)((wid * 16 + l7 + s01 * 8) * (PT * 2)) + s23 * 16;
#pragma unroll
        for (int c = 0; c < 4; c++)
            ldsm_x4(qh[c], base + A_Q + c * 32);
    }

    const int g   = lane >> 2;
    const int tig = lane & 3;
    const int qrow_g  = q0 + wid * 16 + g;
    const unsigned* mrow0 = g_mbits + (size_t)(n * S_LEN + qrow_g) * MWORDS;
    const unsigned* mrow8 = mrow0 + 8 * MWORDS;

    const uint32_t kqoff = (uint32_t)(((lane >> 4) * 8 + l7) * (PT * 2)) + ((lane >> 3) & 1) * 16;
    const uint32_t voff  = (uint32_t)((((lane >> 3) & 1) * 8 + l7) * (PT * 2)) + (lane >> 4) * 16;

    float o[8][4];
#pragma unroll
    for (int j = 0; j < 8; j++)
#pragma unroll
        for (int u = 0; u < 4; u++) o[j][u] = 0.f;
    float lsum_g = 0.f, lsum_8 = 0.f;

    for (int it = 0; it < NIT; it++) {
        const uint32_t kv = smb + ((it & 1) ? A_KV1 : A_KV0);

        CP_WAIT0();
        __syncthreads();

        if (it + 1 < NIT) {
            const size_t gsrc = (size_t)((it + 1) * 32 + str) * HD + soct * 8;
            const uint32_t d = smb + (((it + 1) & 1) ? A_KV1 : A_KV0);
            cp16(d + soff,        K + gsrc);
            cp16(d + KV_V + soff, V + gsrc);
        }
        CP_COMMIT();

        // ---- S = Q K^T (Q pre-scaled by 1/32) ----
        float s[4][4];
#pragma unroll
        for (int j = 0; j < 4; j++)
#pragma unroll
            for (int u = 0; u < 4; u++) s[j][u] = 0.f;

#pragma unroll
        for (int c = 0; c < 4; c++) {
            uint32_t bh0[4], bh1[4];
            const uint32_t ka0 = kv + kqoff + c * 32;
            const uint32_t ka1 = ka0 + (uint32_t)(16 * (PT * 2));
            ldsm_x4(bh0, ka0);
            ldsm_x4(bh1, ka1);
            mma16816(s[0], qh[c], bh0); mma16816(s[1], qh[c], bh0 + 2);
            mma16816(s[2], qh[c], bh1); mma16816(s[3], qh[c], bh1 + 2);
        }

        // ---- softmax in registers (no scale multiply) ----
        const unsigned w0 = mrow0[it];
        const unsigned w8 = mrow8[it];
#pragma unroll
        for (int j = 0; j < 4; j++) {
            const int bit = j * 8 + tig * 2;
            float p0 = __expf(s[j][0]);
            float p1 = __expf(s[j][1]);
            float p2 = __expf(s[j][2]);
            float p3 = __expf(s[j][3]);
            p0 = ((w0 >> bit) & 1u)       ? p0 : 0.f;
            p1 = ((w0 >> (bit + 1)) & 1u) ? p1 : 0.f;
            p2 = ((w8 >> bit) & 1u)       ? p2 : 0.f;
            p3 = ((w8 >> (bit + 1)) & 1u) ? p3 : 0.f;
            lsum_g += p0 + p1;
            lsum_8 += p2 + p3;
            s[j][0] = p0; s[j][1] = p1; s[j][2] = p2; s[j][3] = p3;
        }

        // ---- O += P V ----
#pragma unroll
        for (int c2 = 0; c2 < 2; c2++) {
            uint32_t ah[4];
            ah[0] = pack2h(s[2 * c2][0],     s[2 * c2][1]);
            ah[1] = pack2h(s[2 * c2][2],     s[2 * c2][3]);
            ah[2] = pack2h(s[2 * c2 + 1][0], s[2 * c2 + 1][1]);
            ah[3] = pack2h(s[2 * c2 + 1][2], s[2 * c2 + 1][3]);
#pragma unroll
            for (int jp = 0; jp < 4; jp++) {
                uint32_t bh[4];
                const uint32_t va = kv + KV_V + voff +
                                    (uint32_t)(c2 * 16 * (PT * 2)) + jp * 32;
                ldsm_x4_t(bh, va);
                mma16816(o[2 * jp],     ah, bh);
                mma16816(o[2 * jp + 1], ah, bh + 2);
            }
        }
    }

    // ---- epilogue ----
    lsum_g += __shfl_xor_sync(0xffffffffu, lsum_g, 1);
    lsum_g += __shfl_xor_sync(0xffffffffu, lsum_g, 2);
    lsum_8 += __shfl_xor_sync(0xffffffffu, lsum_8, 1);
    lsum_8 += __shfl_xor_sync(0xffffffffu, lsum_8, 2);
    const float inv_g = 1.0f / lsum_g;
    const float inv_8 = 1.0f / lsum_8;

    const size_t d0 = (size_t)(n * S_LEN + qrow_g) * EMB + h * HD;
    const size_t d8 = d0 + (size_t)8 * EMB;
#pragma unroll
    for (int j = 0; j < 8; j++) {
        const int col = j * 8 + tig * 2;
        *(uint32_t*)(g_ao + d0 + col) = pack2h(o[j][0] * inv_g, o[j][1] * inv_g);
        *(uint32_t*)(g_ao + d8 + col) = pack2h(o[j][2] * inv_8, o[j][3] * inv_8);
    }
}

// ---------------------------------------------------------------------------
// Kernel 3: output projection — A and Wo SINGLE fp16, BK=32, 2-stage ring
// stage: A 0 / B 10240 (pitch 80 B); 2 stages of 20480
// ---------------------------------------------------------------------------
#define OPKB    80
#define OB2_SZ  20480
#define OB2_B   10240
#define OUT2_SMEM (2 * 20480 + 128)
#define ONIT2 (EMB / 32)

__global__ __launch_bounds__(256, 2)
void out_mma_kernel(const float* __restrict__ bo, float* __restrict__ out)
{
    extern __shared__ char sm[];
    const uint32_t smb = smem_u32(sm);

    const int tid = threadIdx.x, wid = tid >> 5, lane = tid & 31;
    const int r0 = blockIdx.y * 128;
    const int e0 = blockIdx.x * 128;
    const int wr = wid & 3;
    const int wc = wid >> 2;

    const int l7  = lane & 7;
    const int s01 = (lane >> 3) & 1;
    const int s23 = lane >> 4;
    const uint32_t aoff = (uint32_t)((l7 + s01 * 8) * OPKB) + s23 * 16;
    const uint32_t boff = (uint32_t)((s23 * 8 + l7) * OPKB) + s01 * 16;

    float acc[2][8][4];
#pragma unroll
    for (int m = 0; m < 2; m++)
#pragma unroll
        for (int j = 0; j < 8; j++)
#pragma unroll
            for (int u = 0; u < 4; u++) acc[m][j][u] = 0.f;

    const int ar0 = tid >> 2,          aq0 = tid & 3;
    const int ar1 = (tid + 256) >> 2,  aq1 = tid & 3;
    const uint32_t os0 = (uint32_t)(ar0 * OPKB + aq0 * 16);
    const uint32_t os1 = (uint32_t)(ar1 * OPKB + aq1 * 16);
    const size_t ag0 = (size_t)(r0 + ar0) * EMB + aq0 * 8;
    const size_t ag1 = (size_t)(r0 + ar1) * EMB + aq1 * 8;
    const size_t bg0 = (size_t)(e0 + ar0) * EMB + aq0 * 8;
    const size_t bg1 = (size_t)(e0 + ar1) * EMB + aq1 * 8;

    {
        const uint32_t d = smb;
        cp16(d + os0,         g_ao + ag0);  cp16(d + os1,         g_ao + ag1);
        cp16(d + OB2_B + os0, g_wo + bg0);  cp16(d + OB2_B + os1, g_wo + bg1);
    }
    CP_COMMIT();

    for (int ic = 0; ic < ONIT2; ic++) {
        const uint32_t buf = smb + (ic & 1) * OB2_SZ;

        CP_WAIT0();
        __syncthreads();

        if (ic + 1 < ONIT2) {
            const int c1 = (ic + 1) * 32;
            const uint32_t d = smb + ((ic + 1) & 1) * OB2_SZ;
            cp16(d + os0,         g_ao + ag0 + c1);  cp16(d + os1,         g_ao + ag1 + c1);
            cp16(d + OB2_B + os0, g_wo + bg0 + c1);  cp16(d + OB2_B + os1, g_wo + bg1 + c1);
        }
        CP_COMMIT();

#pragma unroll
        for (int kk = 0; kk < 2; kk++) {
            uint32_t ah0[4], ah1[4];
            const uint32_t aa0 = buf + (uint32_t)(wr * 32 * OPKB) + aoff + kk * 32;
            const uint32_t aa1 = aa0 + (uint32_t)(16 * OPKB);
            ldsm_x4(ah0, aa0);
            ldsm_x4(ah1, aa1);
#pragma unroll
            for (int jj = 0; jj < 4; jj++) {
                uint32_t bh[4];
                const uint32_t ba = buf + OB2_B +
                    (uint32_t)((wc * 64 + jj * 16) * OPKB) + boff + kk * 32;
                ldsm_x4(bh, ba);
                mma16816(acc[0][2 * jj],     ah0, bh); mma16816(acc[0][2 * jj + 1], ah0, bh + 2);
                mma16816(acc[1][2 * jj],     ah1, bh); mma16816(acc[1][2 * jj + 1], ah1, bh + 2);
            }
        }
    }

    const int g   = lane >> 2;
    const int tig = lane & 3;
#pragma unroll
    for (int m = 0; m < 2; m++) {
        const int row  = r0 + wr * 32 + m * 16 + g;
        const int row8 = row + 8;
#pragma unroll
        for (int jn = 0; jn < 8; jn++) {
            const int col = e0 + wc * 64 + jn * 8 + tig * 2;
            const float2 bb = *(const float2*)(bo + col);
            float2 v0 = make_float2(acc[m][jn][0] + bb.x, acc[m][jn][1] + bb.y);
            float2 v1 = make_float2(acc[m][jn][2] + bb.x, acc[m][jn][3] + bb.y);
            *(float2*)(out + (size_t)row  * EMB + col) = v0;
            *(float2*)(out + (size_t)row8 * EMB + col) = v1;
        }
    }
}

// ---------------------------------------------------------------------------
extern "C" void kernel_launch(void* const* d_in, const int* in_sizes, int n_in,
                              void* d_out, int out_size)
{
    const float* values  = (const float*)d_in[0];
    const float* queries = (const float*)d_in[1];
    const float* keys    = (const float*)d_in[2];
    const int*   mask    = (const int*)  d_in[3];
    const float* Wv      = (const float*)d_in[4];
    const float* Wk      = (const float*)d_in[5];
    const float* Wq      = (const float*)d_in[6];
    const float* Wo      = (const float*)d_in[7];
    const float* bo      = (const float*)d_in[8];
    float* out = (float*)d_out;

    static bool attr_set = false;
    if (!attr_set) {
        cudaFuncSetAttribute(proj_wmma_kernel,
                             cudaFuncAttributeMaxDynamicSharedMemorySize, PJ_SMEM);
        cudaFuncSetAttribute(attn_mma_kernel,
                             cudaFuncAttributeMaxDynamicSharedMemorySize, ATTN_SMEM);
        cudaFuncSetAttribute(out_mma_kernel,
                             cudaFuncAttributeMaxDynamicSharedMemorySize, OUT2_SMEM);
        attr_set = true;
    }

    mask_pack_kernel<<<(N_B * S_LEN * MWORDS * 32) / 256, 256>>>(mask);
    wo_half_kernel<<<(EMB * EMB) / (256 * 8), 256>>>(Wo);

    dim3 pgrid(S_LEN / 128, N_B * HEADS, 3);
    proj_wmma_kernel<<<pgrid, 256, PJ_SMEM>>>(queries, keys, values, Wq, Wk, Wv);

    dim3 agrid(HEADS, S_LEN / 128, N_B);
    attn_mma_kernel<<<agrid, 256, ATTN_SMEM>>>();

    dim3 ggrid(EMB / 128, (N_B * S_LEN) / 128);
    out_mma_kernel<<<ggrid, 256, OUT2_SMEM>>>(bo, out);
}